// round 5
// baseline (speedup 1.0000x reference)
#include <cuda_runtime.h>
#include <cuda_bf16.h>
#include <math.h>

#define BATCH 32
#define NTOK  4096
#define DIM   256
#define M_TOT 672
#define MT    64      // query tile per block
#define NCH   128     // token chunk
#define SQR   264     // smem row stride (halves) for Q
#define SXR   264     // smem row stride for X chunk
#define SPR   136     // smem row stride for P

// ---------------- scratch ----------------
__device__ __nv_bfloat16 g_Qh[M_TOT * DIM];
__device__ float         g_c [M_TOT];
__device__ float g_H[BATCH * M_TOT * DIM];
__device__ float g_part[BATCH * 16 * DIM];
__device__ float g_cnt [BATCH * 16];

// ---------------- helpers ----------------
__device__ __forceinline__ unsigned sm_u32(const void* p) {
    return (unsigned)__cvta_generic_to_shared(p);
}
__device__ __forceinline__ void ldsm4(unsigned r[4], unsigned addr) {
    asm volatile("ldmatrix.sync.aligned.m8n8.x4.shared.b16 {%0,%1,%2,%3},[%4];"
                 : "=r"(r[0]), "=r"(r[1]), "=r"(r[2]), "=r"(r[3]) : "r"(addr));
}
__device__ __forceinline__ void ldsm2(unsigned r[2], unsigned addr) {
    asm volatile("ldmatrix.sync.aligned.m8n8.x2.shared.b16 {%0,%1},[%2];"
                 : "=r"(r[0]), "=r"(r[1]) : "r"(addr));
}
__device__ __forceinline__ void ldsm2t(unsigned r[2], unsigned addr) {
    asm volatile("ldmatrix.sync.aligned.m8n8.x2.trans.shared.b16 {%0,%1},[%2];"
                 : "=r"(r[0]), "=r"(r[1]) : "r"(addr));
}
__device__ __forceinline__ void mma16816(float c[4], const unsigned a[4], const unsigned b[2]) {
    asm volatile(
        "mma.sync.aligned.m16n8k16.row.col.f32.bf16.bf16.f32 "
        "{%0,%1,%2,%3},{%4,%5,%6,%7},{%8,%9},{%0,%1,%2,%3};"
        : "+f"(c[0]), "+f"(c[1]), "+f"(c[2]), "+f"(c[3])
        : "r"(a[0]), "r"(a[1]), "r"(a[2]), "r"(a[3]), "r"(b[0]), "r"(b[1]));
}

// ---------------- prep: Qh = bf16((codes@Wq^T+bq)@Wk / 16), c = q.bk/16 ----------------
__global__ __launch_bounds__(256)
void prep_q(const float* __restrict__ cat, const float* __restrict__ typ,
            const float* __restrict__ var, const float* __restrict__ sp,
            const float* __restrict__ Wcat, const float* __restrict__ bcat,
            const float* __restrict__ Wtype, const float* __restrict__ btype,
            const float* __restrict__ Wvar, const float* __restrict__ bvar,
            const float* __restrict__ Wsp, const float* __restrict__ bsp,
            const float* __restrict__ Wk, const float* __restrict__ bk,
            __nv_bfloat16* __restrict__ Qh, float* __restrict__ cvec)
{
    int m = blockIdx.x;
    const float* codes; const float* Wq; const float* bq;
    if (m < 16)       { codes = cat + m * DIM;         Wq = Wcat;  bq = bcat; }
    else if (m < 144) { codes = typ + (m - 16) * DIM;  Wq = Wtype; bq = btype; }
    else if (m < 656) { codes = var + (m - 144) * DIM; Wq = Wvar;  bq = bvar; }
    else              { codes = sp + (m - 656) * DIM;  Wq = Wsp;   bq = bsp; }

    __shared__ float cs[DIM], qs[DIM], red[256];
    int t = threadIdx.x;
    cs[t] = codes[t];
    __syncthreads();

    int w = t >> 5, l = t & 31;
    for (int j = w; j < DIM; j += 8) {
        const float* wr = Wq + j * DIM;
        float s = 0.f;
        #pragma unroll
        for (int i = 0; i < 8; i++) s += wr[l + 32 * i] * cs[l + 32 * i];
        #pragma unroll
        for (int o = 16; o > 0; o >>= 1) s += __shfl_xor_sync(0xffffffffu, s, o);
        if (l == 0) qs[j] = s + bq[j];
    }
    __syncthreads();

    float a = 0.f;
    for (int j = 0; j < DIM; j++) a += qs[j] * Wk[j * DIM + t];
    Qh[m * DIM + t] = __float2bfloat16(a * 0.0625f);

    red[t] = qs[t] * bk[t];
    __syncthreads();
    for (int s = 128; s > 0; s >>= 1) { if (t < s) red[t] += red[t + s]; __syncthreads(); }
    if (t == 0) cvec[m] = red[0] * 0.0625f;
}

// ---------------- fused flash attention: logits + softmax + P@X ----------------
extern __shared__ char smem_raw[];

__global__ void __launch_bounds__(256, 1)
flash_kernel(const __nv_bfloat16* __restrict__ Qh, const float* __restrict__ cvec,
             const float* __restrict__ X, const unsigned char* __restrict__ mask,
             float* __restrict__ H)
{
    __nv_bfloat16* sQ  = (__nv_bfloat16*)(smem_raw);                 // 64 x 264
    __nv_bfloat16* sXh = (__nv_bfloat16*)(smem_raw + 33792);         // 128 x 264
    __nv_bfloat16* sXl = (__nv_bfloat16*)(smem_raw + 101376);        // 128 x 264
    __nv_bfloat16* sPh = (__nv_bfloat16*)(smem_raw + 168960);        // 64 x 136
    __nv_bfloat16* sPl = (__nv_bfloat16*)(smem_raw + 186368);        // 64 x 136
    float* cvals   = (float*)(smem_raw + 203776);                    // 64
    float* rowmax  = (float*)(smem_raw + 204032);                    // 64
    float* rowsum  = (float*)(smem_raw + 204288);                    // 64
    float* rescale = (float*)(smem_raw + 204544);                    // 64
    float* wpmax   = (float*)(smem_raw + 204800);                    // [4][64]
    float* wpsum   = (float*)(smem_raw + 205824);                    // [4][64]
    unsigned char* maskc = (unsigned char*)(smem_raw + 206848);      // 128

    int mt = blockIdx.x, b = blockIdx.y;
    int t = threadIdx.x, lane = t & 31, w = t >> 5;
    int g = lane >> 2, t4 = lane & 3, l15 = lane & 15;
    int wm = (w >> 2) * 32;      // query-row base for this warp (2 m16 tiles)
    int wn = (w & 3) * 32;       // token base for logits (4 n8 tiles)
    int wd = (w & 3) * 64;       // D base for PV (8 n8 tiles)
    int nw = w & 3;
    int m0 = mt * MT;

    // load Q tile (bf16) + per-row constants
    for (int i = t; i < MT * 32; i += 256) {
        int row = i >> 5, q = i & 31;
        int gm = m0 + row;
        uint4 v = make_uint4(0u, 0u, 0u, 0u);
        if (gm < M_TOT) v = *(const uint4*)(Qh + gm * DIM + q * 8);
        *(uint4*)(sQ + row * SQR + q * 8) = v;
    }
    if (t < MT) {
        int gm = m0 + t;
        cvals[t]  = (gm < M_TOT) ? cvec[gm] : 0.f;
        rowmax[t] = -INFINITY;
        rowsum[t] = 0.f;
    }

    float accH[2][8][4];
    #pragma unroll
    for (int mi = 0; mi < 2; mi++)
        #pragma unroll
        for (int nj = 0; nj < 8; nj++)
            #pragma unroll
            for (int fr = 0; fr < 4; fr++) accH[mi][nj][fr] = 0.f;

    const float* Xb = X + (long)b * NTOK * DIM;
    const unsigned char* mb = mask + (long)b * NTOK;

    unsigned aQB  = sm_u32(sQ  + (wm + l15) * SQR + (lane >> 4) * 8);
    unsigned bKB  = sm_u32(sXh + (wn + (l15 & 7)) * SXR + (l15 >> 3) * 8);
    unsigned aPhB = sm_u32(sPh + (wm + l15) * SPR + (lane >> 4) * 8);
    unsigned aPlB = sm_u32(sPl + (wm + l15) * SPR + (lane >> 4) * 8);
    unsigned bVhB = sm_u32(sXh + l15 * SXR + wd);
    unsigned bVlB = sm_u32(sXl + l15 * SXR + wd);

    for (int kc = 0; kc < NTOK / NCH; kc++) {
        // ---- load X chunk (fp32 -> bf16 hi/lo in smem) + mask ----
        const float4* Xc = (const float4*)(Xb + (long)kc * NCH * DIM);
        #pragma unroll
        for (int i = t; i < NCH * 64; i += 256) {
            int tok = i >> 6, dq = i & 63;
            float4 v = Xc[tok * 64 + dq];
            __nv_bfloat162 h0, h1, l0, l1;
            h0.x = __float2bfloat16(v.x); h0.y = __float2bfloat16(v.y);
            h1.x = __float2bfloat16(v.z); h1.y = __float2bfloat16(v.w);
            l0.x = __float2bfloat16(v.x - __bfloat162float(h0.x));
            l0.y = __float2bfloat16(v.y - __bfloat162float(h0.y));
            l1.x = __float2bfloat16(v.z - __bfloat162float(h1.x));
            l1.y = __float2bfloat16(v.w - __bfloat162float(h1.y));
            int off = tok * SXR + dq * 4;
            *(__nv_bfloat162*)(sXh + off)     = h0;
            *(__nv_bfloat162*)(sXh + off + 2) = h1;
            *(__nv_bfloat162*)(sXl + off)     = l0;
            *(__nv_bfloat162*)(sXl + off + 2) = l1;
        }
        if (t < NCH) maskc[t] = mb[kc * NCH + t];
        __syncthreads();

        // ---- logits: S = Q' @ Xh^T ----
        float accS[2][4][4] = {};
        #pragma unroll
        for (int ks = 0; ks < 16; ks++) {
            unsigned a[2][4], bq2[4][2];
            ldsm4(a[0], aQB + (unsigned)(0 * 16 * SQR + ks * 16) * 2u);
            ldsm4(a[1], aQB + (unsigned)(1 * 16 * SQR + ks * 16) * 2u);
            #pragma unroll
            for (int ni = 0; ni < 4; ni++)
                ldsm2(bq2[ni], bKB + (unsigned)(ni * 8 * SXR + ks * 16) * 2u);
            #pragma unroll
            for (int mi = 0; mi < 2; mi++)
                #pragma unroll
                for (int ni = 0; ni < 4; ni++) mma16816(accS[mi][ni], a[mi], bq2[ni]);
        }

        // ---- epilogue: +c, clip, mask; per-row max ----
        float rmx[2][2];
        #pragma unroll
        for (int mi = 0; mi < 2; mi++) {
            float cv0 = cvals[wm + mi * 16 + g];
            float cv1 = cvals[wm + mi * 16 + g + 8];
            rmx[mi][0] = -INFINITY; rmx[mi][1] = -INFINITY;
            #pragma unroll
            for (int ni = 0; ni < 4; ni++) {
                #pragma unroll
                for (int fr = 0; fr < 4; fr++) {
                    int col = wn + ni * 8 + 2 * t4 + (fr & 1);
                    float x = accS[mi][ni][fr] + ((fr & 2) ? cv1 : cv0);
                    x = fminf(fmaxf(x, -50.f), 50.f);
                    if (!maskc[col]) x = -50.f;
                    accS[mi][ni][fr] = x;
                    if (fr & 2) rmx[mi][1] = fmaxf(rmx[mi][1], x);
                    else        rmx[mi][0] = fmaxf(rmx[mi][0], x);
                }
            }
            #pragma unroll
            for (int h = 0; h < 2; h++) {
                float v = rmx[mi][h];
                v = fmaxf(v, __shfl_xor_sync(0xffffffffu, v, 1));
                v = fmaxf(v, __shfl_xor_sync(0xffffffffu, v, 2));
                rmx[mi][h] = v;
            }
            if (t4 == 0) {
                wpmax[nw * 64 + wm + mi * 16 + g]     = rmx[mi][0];
                wpmax[nw * 64 + wm + mi * 16 + g + 8] = rmx[mi][1];
            }
        }
        __syncthreads();

        if (t < MT) {
            float om = rowmax[t];
            float nm = fmaxf(fmaxf(wpmax[t], wpmax[64 + t]),
                             fmaxf(wpmax[128 + t], wpmax[192 + t]));
            nm = fmaxf(nm, om);
            rescale[t] = __expf(om - nm);   // exp(-inf)=0 on first chunk
            rowmax[t]  = nm;
        }
        __syncthreads();

        // ---- p = exp(logit - max); split hi/lo; rescale accH; row sums ----
        float psum[2][2] = {{0.f, 0.f}, {0.f, 0.f}};
        #pragma unroll
        for (int mi = 0; mi < 2; mi++) {
            int r0 = wm + mi * 16 + g, r1 = r0 + 8;
            float nm0 = rowmax[r0], nm1 = rowmax[r1];
            float rs0 = rescale[r0], rs1 = rescale[r1];
            #pragma unroll
            for (int ni = 0; ni < 4; ni++) {
                float p0 = __expf(accS[mi][ni][0] - nm0);
                float p1 = __expf(accS[mi][ni][1] - nm0);
                float p2 = __expf(accS[mi][ni][2] - nm1);
                float p3 = __expf(accS[mi][ni][3] - nm1);
                psum[mi][0] += p0 + p1;
                psum[mi][1] += p2 + p3;
                int col = wn + ni * 8 + 2 * t4;
                __nv_bfloat162 h01, l01, h23, l23;
                h01.x = __float2bfloat16(p0); h01.y = __float2bfloat16(p1);
                h23.x = __float2bfloat16(p2); h23.y = __float2bfloat16(p3);
                l01.x = __float2bfloat16(p0 - __bfloat162float(h01.x));
                l01.y = __float2bfloat16(p1 - __bfloat162float(h01.y));
                l23.x = __float2bfloat16(p2 - __bfloat162float(h23.x));
                l23.y = __float2bfloat16(p3 - __bfloat162float(h23.y));
                *(__nv_bfloat162*)(sPh + r0 * SPR + col) = h01;
                *(__nv_bfloat162*)(sPh + r1 * SPR + col) = h23;
                *(__nv_bfloat162*)(sPl + r0 * SPR + col) = l01;
                *(__nv_bfloat162*)(sPl + r1 * SPR + col) = l23;
            }
            #pragma unroll
            for (int nj = 0; nj < 8; nj++) {
                accH[mi][nj][0] *= rs0; accH[mi][nj][1] *= rs0;
                accH[mi][nj][2] *= rs1; accH[mi][nj][3] *= rs1;
            }
            #pragma unroll
            for (int h = 0; h < 2; h++) {
                float v = psum[mi][h];
                v += __shfl_xor_sync(0xffffffffu, v, 1);
                v += __shfl_xor_sync(0xffffffffu, v, 2);
                psum[mi][h] = v;
            }
            if (t4 == 0) {
                wpsum[nw * 64 + r0] = psum[mi][0];
                wpsum[nw * 64 + r1] = psum[mi][1];
            }
        }
        __syncthreads();

        if (t < MT)
            rowsum[t] = rowsum[t] * rescale[t] +
                        (wpsum[t] + wpsum[64 + t] + wpsum[128 + t] + wpsum[192 + t]);

        // ---- PV: accH += Ph@Xh + Ph@Xl + Pl@Xh ----
        #pragma unroll
        for (int ks = 0; ks < 8; ks++) {
            unsigned aph[2][4], apl[2][4];
            ldsm4(aph[0], aPhB + (unsigned)(0 * 16 * SPR + ks * 16) * 2u);
            ldsm4(aph[1], aPhB + (unsigned)(1 * 16 * SPR + ks * 16) * 2u);
            ldsm4(apl[0], aPlB + (unsigned)(0 * 16 * SPR + ks * 16) * 2u);
            ldsm4(apl[1], aPlB + (unsigned)(1 * 16 * SPR + ks * 16) * 2u);
            #pragma unroll
            for (int nj = 0; nj < 8; nj++) {
                unsigned bh[2], bl[2];
                ldsm2t(bh, bVhB + (unsigned)(ks * 16 * SXR) * 2u + (unsigned)nj * 16u);
                ldsm2t(bl, bVlB + (unsigned)(ks * 16 * SXR) * 2u + (unsigned)nj * 16u);
                mma16816(accH[0][nj], aph[0], bh);
                mma16816(accH[1][nj], aph[1], bh);
                mma16816(accH[0][nj], aph[0], bl);
                mma16816(accH[1][nj], aph[1], bl);
                mma16816(accH[0][nj], apl[0], bh);
                mma16816(accH[1][nj], apl[1], bh);
            }
        }
        __syncthreads();   // protect smem reuse next chunk
    }

    // ---- normalize by rowsum and store H ----
    #pragma unroll
    for (int mi = 0; mi < 2; mi++) {
        int r0 = wm + mi * 16 + g, r1 = r0 + 8;
        float i0 = 1.f / rowsum[r0];
        float i1 = 1.f / rowsum[r1];
        int gm0 = m0 + r0, gm1 = m0 + r1;
        #pragma unroll
        for (int nj = 0; nj < 8; nj++) {
            int col = wd + nj * 8 + 2 * t4;
            if (gm0 < M_TOT)
                *(float2*)(H + ((long)b * M_TOT + gm0) * DIM + col) =
                    make_float2(accH[mi][nj][0] * i0, accH[mi][nj][1] * i0);
            if (gm1 < M_TOT)
                *(float2*)(H + ((long)b * M_TOT + gm1) * DIM + col) =
                    make_float2(accH[mi][nj][2] * i1, accH[mi][nj][3] * i1);
        }
    }
}

// ---------------- masked position pooling partials ----------------
__global__ __launch_bounds__(256)
void pospool_partial(const float* __restrict__ pos, const unsigned char* __restrict__ mask,
                     float* __restrict__ part, float* __restrict__ cnt)
{
    int s = blockIdx.x, b = blockIdx.y;
    int t = threadIdx.x;
    const float* P = pos + ((long)b * NTOK + s * 256) * DIM;
    const unsigned char* M = mask + (long)b * NTOK + s * 256;
    float acc = 0.f, c = 0.f;
    for (int n = 0; n < 256; n++) {
        float mm = M[n] ? 1.f : 0.f;
        c += mm;
        acc += mm * P[(long)n * DIM + t];
    }
    part[((long)b * 16 + s) * DIM + t] = acc;
    if (t == 0) cnt[b * 16 + s] = c;
}

// ---------------- per-batch tail ----------------
__device__ __forceinline__ float blk_sum(float v, float* red, int t)
{
    __syncthreads();
    red[t] = v; __syncthreads();
    for (int s = 128; s > 0; s >>= 1) { if (t < s) red[t] += red[t + s]; __syncthreads(); }
    float r = red[0]; __syncthreads();
    return r;
}
__device__ __forceinline__ float blk_max(float v, float* red, int t)
{
    __syncthreads();
    red[t] = v; __syncthreads();
    for (int s = 128; s > 0; s >>= 1) { if (t < s) red[t] = fmaxf(red[t], red[t + s]); __syncthreads(); }
    float r = red[0]; __syncthreads();
    return r;
}
__device__ void softmax_sparsify(float* a, int len, float thr, float* red, int t)
{
    float m = -1e30f;
    for (int i = t; i < len; i += 256) m = fmaxf(m, a[i]);
    m = blk_max(m, red, t);
    float s = 0.f;
    for (int i = t; i < len; i += 256) { float e = expf(a[i] - m); a[i] = e; s += e; }
    s = blk_sum(s, red, t);
    float inv = 1.f / s;
    float s2 = 0.f;
    for (int i = t; i < len; i += 256) { float p = a[i] * inv; p = (p > thr) ? p : 0.f; a[i] = p; s2 += p; }
    s2 = blk_sum(s2, red, t);
    float inv2 = 1.f / (s2 + 1e-8f);
    for (int i = t; i < len; i += 256) a[i] *= inv2;
    __syncthreads();
}

__global__ __launch_bounds__(256)
void final_kernel(const float* __restrict__ H, const float* __restrict__ part,
                  const float* __restrict__ cnt, const float* __restrict__ log_tau,
                  const float* __restrict__ Wg1, const float* __restrict__ bg1,
                  const float* __restrict__ Wg2, const float* __restrict__ bg2,
                  const float* __restrict__ Wo,  const float* __restrict__ bo,
                  const float* __restrict__ ln_g, const float* __restrict__ ln_b,
                  const float* __restrict__ lvlw, float* __restrict__ out)
{
    __shared__ float sw[M_TOT];
    __shared__ float red[256];
    __shared__ float wcs[16], wts[128], wvs[512], wss[16];
    __shared__ float coeff[M_TOT];
    __shared__ float xc[512];
    __shared__ float hb[256], gb[256], yb[256], zg[256];
    __shared__ float lw[4];

    int b = blockIdx.x;
    int t = threadIdx.x;
    const float* Hb = H + (long)b * M_TOT * DIM;
    float tau = fminf(fmaxf(expf(log_tau[0]) + 0.1f, 0.1f), 2.0f);

    if (t == 0) {
        float m = fmaxf(fmaxf(lvlw[0], lvlw[1]), fmaxf(lvlw[2], lvlw[3]));
        float e0 = expf(lvlw[0]-m), e1 = expf(lvlw[1]-m), e2 = expf(lvlw[2]-m), e3 = expf(lvlw[3]-m);
        float s = e0+e1+e2+e3;
        lw[0]=e0/s; lw[1]=e1/s; lw[2]=e2/s; lw[3]=e3/s;
    }

    int w = t >> 5, l = t & 31;
    for (int m = w; m < M_TOT; m += 8) {
        const float* hr = Hb + m * DIM;
        float s = 0.f;
        #pragma unroll
        for (int i = 0; i < 8; i++) { float x = hr[l + 32 * i]; s += x * x; }
        #pragma unroll
        for (int o = 16; o > 0; o >>= 1) s += __shfl_xor_sync(0xffffffffu, s, o);
        if (l == 0) sw[m] = sqrtf(s) / tau;
    }
    __syncthreads();

    if (t < 16) wcs[t] = sw[t];
    __syncthreads();
    softmax_sparsify(wcs, 16, 0.1f, red, t);
    if (t < 128) wts[t] = sw[16 + t] * wcs[t >> 3];
    __syncthreads();
    softmax_sparsify(wts, 128, 0.05f, red, t);
    for (int i = t; i < 512; i += 256) wvs[i] = sw[144 + i] * wts[i >> 2];
    __syncthreads();
    softmax_sparsify(wvs, 512, 0.025f, red, t);
    if (t < 16) wss[t] = sw[656 + t];
    __syncthreads();
    softmax_sparsify(wss, 16, 0.1f, red, t);

    for (int i = t; i < M_TOT; i += 256) {
        float c;
        if (i < 16)       c = lw[0] * wcs[i];
        else if (i < 144) c = lw[1] * wts[i - 16];
        else if (i < 656) c = lw[2] * wvs[i - 144];
        else              c = lw[3] * wss[i - 656];
        coeff[i] = c;
    }
    __syncthreads();

    float z = 0.f;
    for (int m = 0; m < M_TOT; m++) z += coeff[m] * Hb[m * DIM + t];
    xc[t] = z;

    float pp = 0.f, cc = 0.f;
    #pragma unroll
    for (int s = 0; s < 16; s++) {
        pp += part[((long)b * 16 + s) * DIM + t];
        cc += cnt[b * 16 + s];
    }
    xc[256 + t] = pp / (cc + 1e-8f);
    __syncthreads();

    for (int j = w; j < 256; j += 8) {
        const float* wr = Wg1 + j * 512;
        float s = 0.f;
        #pragma unroll
        for (int i = 0; i < 16; i++) s += wr[l + 32 * i] * xc[l + 32 * i];
        #pragma unroll
        for (int o = 16; o > 0; o >>= 1) s += __shfl_xor_sync(0xffffffffu, s, o);
        if (l == 0) {
            float x = s + bg1[j];
            hb[j] = 0.5f * x * (1.0f + erff(x * 0.70710678118654752f));
        }
    }
    __syncthreads();

    for (int j = w; j < 256; j += 8) {
        const float* wr = Wg2 + j * 256;
        float s = 0.f;
        #pragma unroll
        for (int i = 0; i < 8; i++) s += wr[l + 32 * i] * hb[l + 32 * i];
        #pragma unroll
        for (int o = 16; o > 0; o >>= 1) s += __shfl_xor_sync(0xffffffffu, s, o);
        if (l == 0) gb[j] = 1.0f / (1.0f + expf(-(s + bg2[j])));
    }
    __syncthreads();

    zg[t] = xc[t] * gb[t];
    __syncthreads();

    for (int j = w; j < 256; j += 8) {
        const float* wr = Wo + j * 256;
        float s = 0.f;
        #pragma unroll
        for (int i = 0; i < 8; i++) s += wr[l + 32 * i] * zg[l + 32 * i];
        #pragma unroll
        for (int o = 16; o > 0; o >>= 1) s += __shfl_xor_sync(0xffffffffu, s, o);
        if (l == 0) yb[j] = s + bo[j];
    }
    __syncthreads();

    float y = yb[t];
    float mu = blk_sum(y, red, t) * (1.0f / 256.0f);
    float d0 = y - mu;
    float var = blk_sum(d0 * d0, red, t) * (1.0f / 256.0f);
    out[(long)b * DIM + t] = d0 * rsqrtf(var + 1e-5f) * ln_g[t] + ln_b[t];
}

// ---------------- launch ----------------
extern "C" void kernel_launch(void* const* d_in, const int* in_sizes, int n_in,
                              void* d_out, int out_size)
{
    const float* X    = (const float*)d_in[0];
    const float* pos  = (const float*)d_in[1];
    const unsigned char* mask = (const unsigned char*)d_in[2];
    const float* cat  = (const float*)d_in[3];
    const float* typ  = (const float*)d_in[4];
    const float* var  = (const float*)d_in[5];
    const float* sp   = (const float*)d_in[6];
    const float* log_tau = (const float*)d_in[7];
    const float* Wk   = (const float*)d_in[8];
    const float* bk   = (const float*)d_in[9];
    const float* Wcat = (const float*)d_in[10];
    const float* bcat = (const float*)d_in[11];
    const float* Wtype= (const float*)d_in[12];
    const float* btype= (const float*)d_in[13];
    const float* Wvar = (const float*)d_in[14];
    const float* bvar = (const float*)d_in[15];
    const float* Wsp  = (const float*)d_in[16];
    const float* bsp  = (const float*)d_in[17];
    const float* Wg1  = (const float*)d_in[18];
    const float* bg1  = (const float*)d_in[19];
    const float* Wg2  = (const float*)d_in[20];
    const float* bg2  = (const float*)d_in[21];
    const float* Wo   = (const float*)d_in[22];
    const float* bo   = (const float*)d_in[23];
    const float* ln_g = (const float*)d_in[24];
    const float* ln_b = (const float*)d_in[25];
    const float* lvlw = (const float*)d_in[26];
    float* out = (float*)d_out;

    __nv_bfloat16 *Qh;
    float *cvec, *H, *part, *cnt;
    cudaGetSymbolAddress((void**)&Qh,   g_Qh);
    cudaGetSymbolAddress((void**)&cvec, g_c);
    cudaGetSymbolAddress((void**)&H,    g_H);
    cudaGetSymbolAddress((void**)&part, g_part);
    cudaGetSymbolAddress((void**)&cnt,  g_cnt);

    const int SMEM_BYTES = 206976;
    cudaFuncSetAttribute(flash_kernel,
                         cudaFuncAttributeMaxDynamicSharedMemorySize, SMEM_BYTES);

    // 1) Q' and c
    prep_q<<<M_TOT, 256>>>(cat, typ, var, sp, Wcat, bcat, Wtype, btype,
                           Wvar, bvar, Wsp, bsp, Wk, bk, Qh, cvec);

    // 2) fused attention
    {
        dim3 grid((M_TOT + MT - 1) / MT, BATCH);
        flash_kernel<<<grid, 256, SMEM_BYTES>>>(Qh, cvec, X, mask, H);
    }

    // 3) position pooling partials
    {
        dim3 grid(16, BATCH);
        pospool_partial<<<grid, 256>>>(pos, mask, part, cnt);
    }

    // 4) per-batch tail
    final_kernel<<<BATCH, 256>>>(H, part, cnt, log_tau,
                                 Wg1, bg1, Wg2, bg2, Wo, bo,
                                 ln_g, ln_b, lvlw, out);
}

// round 6
// speedup vs baseline: 1.5073x; 1.5073x over previous
#include <cuda_runtime.h>
#include <cuda_bf16.h>
#include <math.h>

#define BATCH 32
#define NTOK  4096
#define DIM   256
#define M_TOT 672

// ---------------- scratch ----------------
__device__ __nv_bfloat16 g_Qh[M_TOT * DIM];
__device__ float         g_c [M_TOT];
__device__ __nv_bfloat16 g_S [(long)BATCH * M_TOT * NTOK];
__device__ __nv_bfloat16 g_Gh[(long)BATCH * M_TOT * NTOK];
__device__ __nv_bfloat16 g_Gl[(long)BATCH * M_TOT * NTOK];
__device__ __nv_bfloat16 g_Xh[(long)BATCH * NTOK * DIM];
__device__ __nv_bfloat16 g_Xl[(long)BATCH * NTOK * DIM];
__device__ float g_H[BATCH * M_TOT * DIM];
__device__ float g_sw[BATCH * M_TOT];
__device__ float g_part[BATCH * 16 * DIM];
__device__ float g_cnt [BATCH * 16];

// ---------------- helpers ----------------
__device__ __forceinline__ unsigned sm_u32(const void* p) {
    return (unsigned)__cvta_generic_to_shared(p);
}
__device__ __forceinline__ void ldsm4(unsigned r[4], unsigned addr) {
    asm volatile("ldmatrix.sync.aligned.m8n8.x4.shared.b16 {%0,%1,%2,%3},[%4];"
                 : "=r"(r[0]), "=r"(r[1]), "=r"(r[2]), "=r"(r[3]) : "r"(addr));
}
__device__ __forceinline__ void ldsm2(unsigned r[2], unsigned addr) {
    asm volatile("ldmatrix.sync.aligned.m8n8.x2.shared.b16 {%0,%1},[%2];"
                 : "=r"(r[0]), "=r"(r[1]) : "r"(addr));
}
__device__ __forceinline__ void ldsm2t(unsigned r[2], unsigned addr) {
    asm volatile("ldmatrix.sync.aligned.m8n8.x2.trans.shared.b16 {%0,%1},[%2];"
                 : "=r"(r[0]), "=r"(r[1]) : "r"(addr));
}
__device__ __forceinline__ void mma16816(float c[4], const unsigned a[4], const unsigned b[2]) {
    asm volatile(
        "mma.sync.aligned.m16n8k16.row.col.f32.bf16.bf16.f32 "
        "{%0,%1,%2,%3},{%4,%5,%6,%7},{%8,%9},{%0,%1,%2,%3};"
        : "+f"(c[0]), "+f"(c[1]), "+f"(c[2]), "+f"(c[3])
        : "r"(a[0]), "r"(a[1]), "r"(a[2]), "r"(a[3]), "r"(b[0]), "r"(b[1]));
}
__device__ __forceinline__ unsigned pack_bf2(float a, float b) {
    __nv_bfloat162 t;
    t.x = __float2bfloat16(a); t.y = __float2bfloat16(b);
    return *(unsigned*)&t;
}

// ---------------- X -> hi/lo bf16 ----------------
__global__ __launch_bounds__(256)
void convert_x(const float4* __restrict__ X, unsigned* __restrict__ Xh,
               unsigned* __restrict__ Xl)
{
    long i = (long)blockIdx.x * 256 + threadIdx.x;   // over float4s
    float4 v = X[i];
    float hx = __bfloat162float(__float2bfloat16(v.x));
    float hy = __bfloat162float(__float2bfloat16(v.y));
    float hz = __bfloat162float(__float2bfloat16(v.z));
    float hw = __bfloat162float(__float2bfloat16(v.w));
    uint2 ho, lo;
    ho.x = pack_bf2(v.x, v.y);       ho.y = pack_bf2(v.z, v.w);
    lo.x = pack_bf2(v.x - hx, v.y - hy); lo.y = pack_bf2(v.z - hz, v.w - hw);
    *(uint2*)(Xh + i * 2) = ho;
    *(uint2*)(Xl + i * 2) = lo;
}

// ---------------- prep: Qh = bf16((codes@Wq^T+bq)@Wk / 16), c = q.bk/16 ----------------
__global__ __launch_bounds__(256)
void prep_q(const float* __restrict__ cat, const float* __restrict__ typ,
            const float* __restrict__ var, const float* __restrict__ sp,
            const float* __restrict__ Wcat, const float* __restrict__ bcat,
            const float* __restrict__ Wtype, const float* __restrict__ btype,
            const float* __restrict__ Wvar, const float* __restrict__ bvar,
            const float* __restrict__ Wsp, const float* __restrict__ bsp,
            const float* __restrict__ Wk, const float* __restrict__ bk,
            __nv_bfloat16* __restrict__ Qh, float* __restrict__ cvec)
{
    int m = blockIdx.x;
    const float* codes; const float* Wq; const float* bq;
    if (m < 16)       { codes = cat + m * DIM;         Wq = Wcat;  bq = bcat; }
    else if (m < 144) { codes = typ + (m - 16) * DIM;  Wq = Wtype; bq = btype; }
    else if (m < 656) { codes = var + (m - 144) * DIM; Wq = Wvar;  bq = bvar; }
    else              { codes = sp + (m - 656) * DIM;  Wq = Wsp;   bq = bsp; }

    __shared__ float cs[DIM], qs[DIM], red[256];
    int t = threadIdx.x;
    cs[t] = codes[t];
    __syncthreads();

    int w = t >> 5, l = t & 31;
    for (int j = w; j < DIM; j += 8) {
        const float* wr = Wq + j * DIM;
        float s = 0.f;
        #pragma unroll
        for (int i = 0; i < 8; i++) s += wr[l + 32 * i] * cs[l + 32 * i];
        #pragma unroll
        for (int o = 16; o > 0; o >>= 1) s += __shfl_xor_sync(0xffffffffu, s, o);
        if (l == 0) qs[j] = s + bq[j];
    }
    __syncthreads();

    float a = 0.f;
    for (int j = 0; j < DIM; j++) a += qs[j] * Wk[j * DIM + t];
    Qh[m * DIM + t] = __float2bfloat16(a * 0.0625f);

    red[t] = qs[t] * bk[t];
    __syncthreads();
    for (int s = 128; s > 0; s >>= 1) { if (t < s) red[t] += red[t + s]; __syncthreads(); }
    if (t == 0) cvec[m] = red[0] * 0.0625f;
}

// ---------------- logits: S[b][m][n] = bf16(clip(Qh[m].Xh[b][n] + c[m])) ----------------
__global__ __launch_bounds__(256)
void logits_mma(const __nv_bfloat16* __restrict__ Qh,
                const __nv_bfloat16* __restrict__ Xh,
                __nv_bfloat16* __restrict__ S,
                const float* __restrict__ cvec,
                const unsigned char* __restrict__ mask)
{
    const int SK = 40;
    __shared__ __nv_bfloat16 sA[128 * SK];
    __shared__ __nv_bfloat16 sB[128 * SK];

    int b = blockIdx.z;
    int m0 = blockIdx.y * 128, n0 = blockIdx.x * 128;
    const __nv_bfloat16* Xb = Xh + (long)b * NTOK * DIM;
    int t = threadIdx.x, lane = t & 31, w = t >> 5;
    int wm = (w >> 2) * 64, wn = (w & 3) * 32;

    uint4 ra[2], rb[2];
    auto gload = [&](int kt) {
        #pragma unroll
        for (int i = 0; i < 2; i++) {
            int c = t + i * 256;
            int row = c >> 2, kc = (c & 3) * 8;
            int gm = m0 + row;
            ra[i] = make_uint4(0u, 0u, 0u, 0u);
            if (gm < M_TOT) ra[i] = *(const uint4*)(Qh + gm * DIM + kt * 32 + kc);
            rb[i] = *(const uint4*)(Xb + (long)(n0 + row) * DIM + kt * 32 + kc);
        }
    };
    auto sstore = [&]() {
        #pragma unroll
        for (int i = 0; i < 2; i++) {
            int c = t + i * 256;
            int row = c >> 2, kc = (c & 3) * 8;
            *(uint4*)(sA + row * SK + kc) = ra[i];
            *(uint4*)(sB + row * SK + kc) = rb[i];
        }
    };

    int l15 = lane & 15;
    unsigned aBase = sm_u32(sA + (wm + l15) * SK + (lane >> 4) * 8);
    unsigned bBase = sm_u32(sB + (wn + (l15 & 7)) * SK + (l15 >> 3) * 8);

    float acc[4][4][4] = {};
    gload(0);
    for (int kt = 0; kt < 8; kt++) {
        __syncthreads();
        sstore();
        __syncthreads();
        if (kt < 7) gload(kt + 1);
        #pragma unroll
        for (int ks = 0; ks < 2; ks++) {
            unsigned a[4][4], bf[4][2];
            #pragma unroll
            for (int mi = 0; mi < 4; mi++) ldsm4(a[mi], aBase + (unsigned)(mi * 16 * SK + ks * 16) * 2u);
            #pragma unroll
            for (int ni = 0; ni < 4; ni++) ldsm2(bf[ni], bBase + (unsigned)(ni * 8 * SK + ks * 16) * 2u);
            #pragma unroll
            for (int mi = 0; mi < 4; mi++)
                #pragma unroll
                for (int ni = 0; ni < 4; ni++) mma16816(acc[mi][ni], a[mi], bf[ni]);
        }
    }

    const unsigned char* mrow = mask + (long)b * NTOK;
    #pragma unroll
    for (int mi = 0; mi < 4; mi++) {
        #pragma unroll
        for (int r = 0; r < 2; r++) {
            int gm = m0 + wm + mi * 16 + (lane >> 2) + r * 8;
            if (gm >= M_TOT) continue;
            float cv = cvec[gm];
            __nv_bfloat16* srow = S + ((long)b * M_TOT + gm) * NTOK;
            #pragma unroll
            for (int ni = 0; ni < 4; ni++) {
                int col = n0 + wn + ni * 8 + (lane & 3) * 2;
                float x0 = acc[mi][ni][r * 2 + 0] + cv;
                float x1 = acc[mi][ni][r * 2 + 1] + cv;
                x0 = fminf(fmaxf(x0, -50.f), 50.f);
                x1 = fminf(fmaxf(x1, -50.f), 50.f);
                if (!mrow[col])     x0 = -50.f;
                if (!mrow[col + 1]) x1 = -50.f;
                __nv_bfloat162 v;
                v.x = __float2bfloat16(x0); v.y = __float2bfloat16(x1);
                *(__nv_bfloat162*)(srow + col) = v;
            }
        }
    }
}

// ---------------- softmax rows -> Gh/Gl (hi/lo bf16) ----------------
__global__ __launch_bounds__(256)
void softmax_rows(const __nv_bfloat16* __restrict__ S,
                  __nv_bfloat16* __restrict__ Gh, __nv_bfloat16* __restrict__ Gl)
{
    long row = blockIdx.x;
    const __nv_bfloat162* p = (const __nv_bfloat162*)(S + row * (long)NTOK);
    __nv_bfloat162* gh = (__nv_bfloat162*)(Gh + row * (long)NTOK);
    __nv_bfloat162* gl = (__nv_bfloat162*)(Gl + row * (long)NTOK);
    int t = threadIdx.x;
    float v[16];
    float mx = -1e30f;
    #pragma unroll
    for (int i = 0; i < 8; i++) {
        __nv_bfloat162 x = p[t + 256 * i];
        v[2 * i]     = __bfloat162float(x.x);
        v[2 * i + 1] = __bfloat162float(x.y);
        mx = fmaxf(mx, fmaxf(v[2 * i], v[2 * i + 1]));
    }
    __shared__ float red[256];
    red[t] = mx; __syncthreads();
    for (int s = 128; s > 0; s >>= 1) { if (t < s) red[t] = fmaxf(red[t], red[t + s]); __syncthreads(); }
    mx = red[0]; __syncthreads();
    float sum = 0.f;
    #pragma unroll
    for (int i = 0; i < 16; i++) { v[i] = expf(v[i] - mx); sum += v[i]; }
    red[t] = sum; __syncthreads();
    for (int s = 128; s > 0; s >>= 1) { if (t < s) red[t] += red[t + s]; __syncthreads(); }
    float inv = 1.0f / red[0];
    #pragma unroll
    for (int i = 0; i < 8; i++) {
        float g0 = v[2 * i] * inv, g1 = v[2 * i + 1] * inv;
        __nv_bfloat162 h, l;
        h.x = __float2bfloat16(g0); h.y = __float2bfloat16(g1);
        l.x = __float2bfloat16(g0 - __bfloat162float(h.x));
        l.y = __float2bfloat16(g1 - __bfloat162float(h.y));
        gh[t + 256 * i] = h;
        gl[t + 256 * i] = l;
    }
}

// ---------------- H = G @ X  (split-3 bf16) ----------------
__global__ __launch_bounds__(256)
void h_mma(const __nv_bfloat16* __restrict__ Gh, const __nv_bfloat16* __restrict__ Gl,
           const __nv_bfloat16* __restrict__ Xh, const __nv_bfloat16* __restrict__ Xl,
           float* __restrict__ H)
{
    const int SK = 40, SN = 136;
    __shared__ __nv_bfloat16 sAh[128 * SK];
    __shared__ __nv_bfloat16 sAl[128 * SK];
    __shared__ __nv_bfloat16 sBh[32 * SN];
    __shared__ __nv_bfloat16 sBl[32 * SN];

    int b = blockIdx.z;
    int m0 = blockIdx.y * 128, n0 = blockIdx.x * 128;
    const __nv_bfloat16* Ghb = Gh + (long)b * M_TOT * NTOK;
    const __nv_bfloat16* Glb = Gl + (long)b * M_TOT * NTOK;
    const __nv_bfloat16* Xhb = Xh + (long)b * NTOK * DIM;
    const __nv_bfloat16* Xlb = Xl + (long)b * NTOK * DIM;
    int t = threadIdx.x, lane = t & 31, w = t >> 5;
    int wm = (w >> 2) * 64, wn = (w & 3) * 32;

    uint4 rah[2], ral[2], rbh[2], rbl[2];
    auto gload = [&](int kt) {
        #pragma unroll
        for (int i = 0; i < 2; i++) {
            int c = t + i * 256;
            {
                int row = c >> 2, kc = (c & 3) * 8;
                int gm = m0 + row;
                rah[i] = make_uint4(0u, 0u, 0u, 0u);
                ral[i] = rah[i];
                if (gm < M_TOT) {
                    long off = (long)gm * NTOK + kt * 32 + kc;
                    rah[i] = *(const uint4*)(Ghb + off);
                    ral[i] = *(const uint4*)(Glb + off);
                }
            }
            {
                int kr = c >> 4, nc = (c & 15) * 8;
                long off = (long)(kt * 32 + kr) * DIM + n0 + nc;
                rbh[i] = *(const uint4*)(Xhb + off);
                rbl[i] = *(const uint4*)(Xlb + off);
            }
        }
    };
    auto sstore = [&]() {
        #pragma unroll
        for (int i = 0; i < 2; i++) {
            int c = t + i * 256;
            int row = c >> 2, kc = (c & 3) * 8;
            *(uint4*)(sAh + row * SK + kc) = rah[i];
            *(uint4*)(sAl + row * SK + kc) = ral[i];
            int kr = c >> 4, nc = (c & 15) * 8;
            *(uint4*)(sBh + kr * SN + nc) = rbh[i];
            *(uint4*)(sBl + kr * SN + nc) = rbl[i];
        }
    };

    int l15 = lane & 15;
    unsigned ahB = sm_u32(sAh + (wm + l15) * SK + (lane >> 4) * 8);
    unsigned alB = sm_u32(sAl + (wm + l15) * SK + (lane >> 4) * 8);
    unsigned bhB = sm_u32(sBh + l15 * SN + wn);
    unsigned blB = sm_u32(sBl + l15 * SN + wn);

    float acc[4][4][4] = {};
    gload(0);
    for (int kt = 0; kt < NTOK / 32; kt++) {
        __syncthreads();
        sstore();
        __syncthreads();
        if (kt < NTOK / 32 - 1) gload(kt + 1);
        #pragma unroll
        for (int ks = 0; ks < 2; ks++) {
            unsigned ah[4][4], al[4][4], bh[4][2], bl[4][2];
            #pragma unroll
            for (int mi = 0; mi < 4; mi++) ldsm4(ah[mi], ahB + (unsigned)(mi * 16 * SK + ks * 16) * 2u);
            #pragma unroll
            for (int ni = 0; ni < 4; ni++) ldsm2t(bh[ni], bhB + (unsigned)(ks * 16 * SN) * 2u + (unsigned)ni * 16u);
            #pragma unroll
            for (int mi = 0; mi < 4; mi++)
                #pragma unroll
                for (int ni = 0; ni < 4; ni++) mma16816(acc[mi][ni], ah[mi], bh[ni]);
            #pragma unroll
            for (int ni = 0; ni < 4; ni++) ldsm2t(bl[ni], blB + (unsigned)(ks * 16 * SN) * 2u + (unsigned)ni * 16u);
            #pragma unroll
            for (int mi = 0; mi < 4; mi++)
                #pragma unroll
                for (int ni = 0; ni < 4; ni++) mma16816(acc[mi][ni], ah[mi], bl[ni]);
            #pragma unroll
            for (int mi = 0; mi < 4; mi++) ldsm4(al[mi], alB + (unsigned)(mi * 16 * SK + ks * 16) * 2u);
            #pragma unroll
            for (int mi = 0; mi < 4; mi++)
                #pragma unroll
                for (int ni = 0; ni < 4; ni++) mma16816(acc[mi][ni], al[mi], bh[ni]);
        }
    }

    #pragma unroll
    for (int mi = 0; mi < 4; mi++) {
        #pragma unroll
        for (int r = 0; r < 2; r++) {
            int gm = m0 + wm + mi * 16 + (lane >> 2) + r * 8;
            if (gm >= M_TOT) continue;
            float* hrow = H + ((long)b * M_TOT + gm) * DIM;
            #pragma unroll
            for (int ni = 0; ni < 4; ni++) {
                int col = n0 + wn + ni * 8 + (lane & 3) * 2;
                *(float2*)(hrow + col) =
                    make_float2(acc[mi][ni][r * 2 + 0], acc[mi][ni][r * 2 + 1]);
            }
        }
    }
}

// ---------------- row norms: sw[b][m] = ||H[b,m]|| / tau ----------------
__global__ __launch_bounds__(256)
void norms_kernel(const float* __restrict__ H, const float* __restrict__ log_tau,
                  float* __restrict__ sw)
{
    int b = blockIdx.y;
    int m = blockIdx.x * 8 + (threadIdx.x >> 5);
    int l = threadIdx.x & 31;
    float tau = fminf(fmaxf(expf(log_tau[0]) + 0.1f, 0.1f), 2.0f);
    const float* hr = H + ((long)b * M_TOT + m) * DIM;
    float s = 0.f;
    #pragma unroll
    for (int i = 0; i < 8; i++) { float x = hr[l + 32 * i]; s += x * x; }
    #pragma unroll
    for (int o = 16; o > 0; o >>= 1) s += __shfl_xor_sync(0xffffffffu, s, o);
    if (l == 0) sw[b * M_TOT + m] = sqrtf(s) / tau;
}

// ---------------- per-batch tail ----------------
__device__ __forceinline__ float blk_sum(float v, float* red, int t)
{
    __syncthreads();
    red[t] = v; __syncthreads();
    for (int s = 128; s > 0; s >>= 1) { if (t < s) red[t] += red[t + s]; __syncthreads(); }
    float r = red[0]; __syncthreads();
    return r;
}
__device__ __forceinline__ float blk_max(float v, float* red, int t)
{
    __syncthreads();
    red[t] = v; __syncthreads();
    for (int s = 128; s > 0; s >>= 1) { if (t < s) red[t] = fmaxf(red[t], red[t + s]); __syncthreads(); }
    float r = red[0]; __syncthreads();
    return r;
}
__device__ void softmax_sparsify(float* a, int len, float thr, float* red, int t)
{
    float m = -1e30f;
    for (int i = t; i < len; i += 256) m = fmaxf(m, a[i]);
    m = blk_max(m, red, t);
    float s = 0.f;
    for (int i = t; i < len; i += 256) { float e = expf(a[i] - m); a[i] = e; s += e; }
    s = blk_sum(s, red, t);
    float inv = 1.f / s;
    float s2 = 0.f;
    for (int i = t; i < len; i += 256) { float p = a[i] * inv; p = (p > thr) ? p : 0.f; a[i] = p; s2 += p; }
    s2 = blk_sum(s2, red, t);
    float inv2 = 1.f / (s2 + 1e-8f);
    for (int i = t; i < len; i += 256) a[i] *= inv2;
    __syncthreads();
}

__global__ __launch_bounds__(256)
void final_kernel(const float* __restrict__ H, const float* __restrict__ swg,
                  const float* __restrict__ part,
                  const float* __restrict__ cnt,
                  const float* __restrict__ Wg1, const float* __restrict__ bg1,
                  const float* __restrict__ Wg2, const float* __restrict__ bg2,
                  const float* __restrict__ Wo,  const float* __restrict__ bo,
                  const float* __restrict__ ln_g, const float* __restrict__ ln_b,
                  const float* __restrict__ lvlw, float* __restrict__ out)
{
    __shared__ float red[256];
    __shared__ float wcs[16], wts[128], wvs[512], wss[16];
    __shared__ float coeff[M_TOT];
    __shared__ float xc[512];
    __shared__ float hb[256], gb[256], yb[256], zg[256];
    __shared__ float lw[4];

    int b = blockIdx.x;
    int t = threadIdx.x;
    const float* Hb = H + (long)b * M_TOT * DIM;
    const float* sw = swg + b * M_TOT;

    if (t == 0) {
        float m = fmaxf(fmaxf(lvlw[0], lvlw[1]), fmaxf(lvlw[2], lvlw[3]));
        float e0 = expf(lvlw[0]-m), e1 = expf(lvlw[1]-m), e2 = expf(lvlw[2]-m), e3 = expf(lvlw[3]-m);
        float s = e0+e1+e2+e3;
        lw[0]=e0/s; lw[1]=e1/s; lw[2]=e2/s; lw[3]=e3/s;
    }

    if (t < 16) wcs[t] = sw[t];
    __syncthreads();
    softmax_sparsify(wcs, 16, 0.1f, red, t);
    if (t < 128) wts[t] = sw[16 + t] * wcs[t >> 3];
    __syncthreads();
    softmax_sparsify(wts, 128, 0.05f, red, t);
    for (int i = t; i < 512; i += 256) wvs[i] = sw[144 + i] * wts[i >> 2];
    __syncthreads();
    softmax_sparsify(wvs, 512, 0.025f, red, t);
    if (t < 16) wss[t] = sw[656 + t];
    __syncthreads();
    softmax_sparsify(wss, 16, 0.1f, red, t);

    for (int i = t; i < M_TOT; i += 256) {
        float c;
        if (i < 16)       c = lw[0] * wcs[i];
        else if (i < 144) c = lw[1] * wts[i - 16];
        else if (i < 656) c = lw[2] * wvs[i - 144];
        else              c = lw[3] * wss[i - 656];
        coeff[i] = c;
    }
    __syncthreads();

    // z[d] = sum_m coeff[m] * H[m][d]  -- 8 independent accumulators (MLP 8)
    {
        float z0 = 0.f, z1 = 0.f, z2 = 0.f, z3 = 0.f;
        float z4 = 0.f, z5 = 0.f, z6 = 0.f, z7 = 0.f;
        #pragma unroll 2
        for (int m = 0; m < M_TOT; m += 8) {
            z0 += coeff[m]     * Hb[(m)     * DIM + t];
            z1 += coeff[m + 1] * Hb[(m + 1) * DIM + t];
            z2 += coeff[m + 2] * Hb[(m + 2) * DIM + t];
            z3 += coeff[m + 3] * Hb[(m + 3) * DIM + t];
            z4 += coeff[m + 4] * Hb[(m + 4) * DIM + t];
            z5 += coeff[m + 5] * Hb[(m + 5) * DIM + t];
            z6 += coeff[m + 6] * Hb[(m + 6) * DIM + t];
            z7 += coeff[m + 7] * Hb[(m + 7) * DIM + t];
        }
        xc[t] = ((z0 + z1) + (z2 + z3)) + ((z4 + z5) + (z6 + z7));
    }

    float pp = 0.f, cc = 0.f;
    #pragma unroll
    for (int s = 0; s < 16; s++) {
        pp += part[((long)b * 16 + s) * DIM + t];
        cc += cnt[b * 16 + s];
    }
    xc[256 + t] = pp / (cc + 1e-8f);
    __syncthreads();

    int w = t >> 5, l = t & 31;
    for (int j = w; j < 256; j += 8) {
        const float* wr = Wg1 + j * 512;
        float s = 0.f;
        #pragma unroll
        for (int i = 0; i < 16; i++) s += wr[l + 32 * i] * xc[l + 32 * i];
        #pragma unroll
        for (int o = 16; o > 0; o >>= 1) s += __shfl_xor_sync(0xffffffffu, s, o);
        if (l == 0) {
            float x = s + bg1[j];
            hb[j] = 0.5f * x * (1.0f + erff(x * 0.70710678118654752f));
        }
    }
    __syncthreads();

    for (int j = w; j < 256; j += 8) {
        const float* wr = Wg2 + j * 256;
        float s = 0.f;
        #pragma unroll
        for (int i = 0; i < 8; i++) s += wr[l + 32 * i] * hb[l + 32 * i];
        #pragma unroll
        for (int o = 16; o > 0; o >>= 1) s += __shfl_xor_sync(0xffffffffu, s, o);
        if (l == 0) gb[j] = 1.0f / (1.0f + expf(-(s + bg2[j])));
    }
    __syncthreads();

    zg[t] = xc[t] * gb[t];
    __syncthreads();

    for (int j = w; j < 256; j += 8) {
        const float* wr = Wo + j * 256;
        float s = 0.f;
        #pragma unroll
        for (int i = 0; i < 8; i++) s += wr[l + 32 * i] * zg[l + 32 * i];
        #pragma unroll
        for (int o = 16; o > 0; o >>= 1) s += __shfl_xor_sync(0xffffffffu, s, o);
        if (l == 0) yb[j] = s + bo[j];
    }
    __syncthreads();

    float y = yb[t];
    float mu = blk_sum(y, red, t) * (1.0f / 256.0f);
    float d0 = y - mu;
    float var = blk_sum(d0 * d0, red, t) * (1.0f / 256.0f);
    out[(long)b * DIM + t] = d0 * rsqrtf(var + 1e-5f) * ln_g[t] + ln_b[t];
}

// ---------------- masked position pooling partials ----------------
__global__ __launch_bounds__(256)
void pospool_partial(const float* __restrict__ pos, const unsigned char* __restrict__ mask,
                     float* __restrict__ part, float* __restrict__ cnt)
{
    int s = blockIdx.x, b = blockIdx.y;
    int t = threadIdx.x;
    const float* P = pos + ((long)b * NTOK + s * 256) * DIM;
    const unsigned char* M = mask + (long)b * NTOK + s * 256;
    float acc = 0.f, c = 0.f;
    for (int n = 0; n < 256; n++) {
        float mm = M[n] ? 1.f : 0.f;
        c += mm;
        acc += mm * P[(long)n * DIM + t];
    }
    part[((long)b * 16 + s) * DIM + t] = acc;
    if (t == 0) cnt[b * 16 + s] = c;
}

// ---------------- launch ----------------
extern "C" void kernel_launch(void* const* d_in, const int* in_sizes, int n_in,
                              void* d_out, int out_size)
{
    const float* X    = (const float*)d_in[0];
    const float* pos  = (const float*)d_in[1];
    const unsigned char* mask = (const unsigned char*)d_in[2];
    const float* cat  = (const float*)d_in[3];
    const float* typ  = (const float*)d_in[4];
    const float* var  = (const float*)d_in[5];
    const float* sp   = (const float*)d_in[6];
    const float* log_tau = (const float*)d_in[7];
    const float* Wk   = (const float*)d_in[8];
    const float* bk   = (const float*)d_in[9];
    const float* Wcat = (const float*)d_in[10];
    const float* bcat = (const float*)d_in[11];
    const float* Wtype= (const float*)d_in[12];
    const float* btype= (const float*)d_in[13];
    const float* Wvar = (const float*)d_in[14];
    const float* bvar = (const float*)d_in[15];
    const float* Wsp  = (const float*)d_in[16];
    const float* bsp  = (const float*)d_in[17];
    const float* Wg1  = (const float*)d_in[18];
    const float* bg1  = (const float*)d_in[19];
    const float* Wg2  = (const float*)d_in[20];
    const float* bg2  = (const float*)d_in[21];
    const float* Wo   = (const float*)d_in[22];
    const float* bo   = (const float*)d_in[23];
    const float* ln_g = (const float*)d_in[24];
    const float* ln_b = (const float*)d_in[25];
    const float* lvlw = (const float*)d_in[26];
    float* out = (float*)d_out;

    __nv_bfloat16 *Qh, *S, *Gh, *Gl, *Xh, *Xl;
    float *cvec, *H, *sw, *part, *cnt;
    cudaGetSymbolAddress((void**)&Qh,   g_Qh);
    cudaGetSymbolAddress((void**)&cvec, g_c);
    cudaGetSymbolAddress((void**)&S,    g_S);
    cudaGetSymbolAddress((void**)&Gh,   g_Gh);
    cudaGetSymbolAddress((void**)&Gl,   g_Gl);
    cudaGetSymbolAddress((void**)&Xh,   g_Xh);
    cudaGetSymbolAddress((void**)&Xl,   g_Xl);
    cudaGetSymbolAddress((void**)&H,    g_H);
    cudaGetSymbolAddress((void**)&sw,   g_sw);
    cudaGetSymbolAddress((void**)&part, g_part);
    cudaGetSymbolAddress((void**)&cnt,  g_cnt);

    // 1) X -> hi/lo bf16
    {
        long n4 = (long)BATCH * NTOK * DIM / 4;
        convert_x<<<(unsigned)(n4 / 256), 256>>>((const float4*)X,
                                                 (unsigned*)Xh, (unsigned*)Xl);
    }

    // 2) Q' and c
    prep_q<<<M_TOT, 256>>>(cat, typ, var, sp, Wcat, bcat, Wtype, btype,
                           Wvar, bvar, Wsp, bsp, Wk, bk, Qh, cvec);

    // 3) logits (bf16 tensor-core GEMM, fused epilogue)
    {
        dim3 grid(NTOK / 128, (M_TOT + 127) / 128, BATCH);
        logits_mma<<<grid, 256>>>(Qh, Xh, S, cvec, mask);
    }

    // 4) softmax -> Gh/Gl
    softmax_rows<<<BATCH * M_TOT, 256>>>(S, Gh, Gl);

    // 5) H = G @ X (split-3 bf16 tensor-core GEMM)
    {
        dim3 grid(DIM / 128, (M_TOT + 127) / 128, BATCH);
        h_mma<<<grid, 256>>>(Gh, Gl, Xh, Xl, H);
    }

    // 6) position pooling partials
    {
        dim3 grid(16, BATCH);
        pospool_partial<<<grid, 256>>>(pos, mask, part, cnt);
    }

    // 7) row norms (full-chip parallel)
    {
        dim3 grid(M_TOT / 8, BATCH);
        norms_kernel<<<grid, 256>>>(H, log_tau, sw);
    }

    // 8) per-batch tail
    final_kernel<<<BATCH, 256>>>(H, sw, part, cnt,
                                 Wg1, bg1, Wg2, bg2, Wo, bo,
                                 ln_g, ln_b, lvlw, out);
}

// round 7
// speedup vs baseline: 1.5090x; 1.0011x over previous
#include <cuda_runtime.h>
#include <cuda_bf16.h>
#include <math.h>

#define BATCH 32
#define NTOK  4096
#define DIM   256
#define M_TOT 672

// ---------------- scratch ----------------
__device__ __nv_bfloat16 g_Qh[M_TOT * DIM];
__device__ float         g_c [M_TOT];
__device__ __nv_bfloat16 g_Eh[(long)BATCH * M_TOT * NTOK];   // exp(logit) hi
__device__ __nv_bfloat16 g_El[(long)BATCH * M_TOT * NTOK];   // exp(logit) lo
__device__ __nv_bfloat16 g_Xh[(long)BATCH * NTOK * DIM];
__device__ __nv_bfloat16 g_Xl[(long)BATCH * NTOK * DIM];
__device__ float g_rs[BATCH * M_TOT];                        // row sums of exp
__device__ float g_H[BATCH * M_TOT * DIM];
__device__ float g_sw[BATCH * M_TOT];
__device__ float g_part[BATCH * 16 * DIM];
__device__ float g_cnt [BATCH * 16];

// ---------------- helpers ----------------
__device__ __forceinline__ unsigned sm_u32(const void* p) {
    return (unsigned)__cvta_generic_to_shared(p);
}
__device__ __forceinline__ void ldsm4(unsigned r[4], unsigned addr) {
    asm volatile("ldmatrix.sync.aligned.m8n8.x4.shared.b16 {%0,%1,%2,%3},[%4];"
                 : "=r"(r[0]), "=r"(r[1]), "=r"(r[2]), "=r"(r[3]) : "r"(addr));
}
__device__ __forceinline__ void ldsm2(unsigned r[2], unsigned addr) {
    asm volatile("ldmatrix.sync.aligned.m8n8.x2.shared.b16 {%0,%1},[%2];"
                 : "=r"(r[0]), "=r"(r[1]) : "r"(addr));
}
__device__ __forceinline__ void ldsm2t(unsigned r[2], unsigned addr) {
    asm volatile("ldmatrix.sync.aligned.m8n8.x2.trans.shared.b16 {%0,%1},[%2];"
                 : "=r"(r[0]), "=r"(r[1]) : "r"(addr));
}
__device__ __forceinline__ void mma16816(float c[4], const unsigned a[4], const unsigned b[2]) {
    asm volatile(
        "mma.sync.aligned.m16n8k16.row.col.f32.bf16.bf16.f32 "
        "{%0,%1,%2,%3},{%4,%5,%6,%7},{%8,%9},{%0,%1,%2,%3};"
        : "+f"(c[0]), "+f"(c[1]), "+f"(c[2]), "+f"(c[3])
        : "r"(a[0]), "r"(a[1]), "r"(a[2]), "r"(a[3]), "r"(b[0]), "r"(b[1]));
}
__device__ __forceinline__ unsigned pack_bf2(float a, float b) {
    __nv_bfloat162 t;
    t.x = __float2bfloat16(a); t.y = __float2bfloat16(b);
    return *(unsigned*)&t;
}

// ---------------- zero rowsums ----------------
__global__ __launch_bounds__(256)
void rs_zero(float* __restrict__ rs)
{
    rs[blockIdx.x * 256 + threadIdx.x] = 0.f;
}

// ---------------- X -> hi/lo bf16 ----------------
__global__ __launch_bounds__(256)
void convert_x(const float4* __restrict__ X, unsigned* __restrict__ Xh,
               unsigned* __restrict__ Xl)
{
    long i = (long)blockIdx.x * 256 + threadIdx.x;   // over float4s
    float4 v = X[i];
    float hx = __bfloat162float(__float2bfloat16(v.x));
    float hy = __bfloat162float(__float2bfloat16(v.y));
    float hz = __bfloat162float(__float2bfloat16(v.z));
    float hw = __bfloat162float(__float2bfloat16(v.w));
    uint2 ho, lo;
    ho.x = pack_bf2(v.x, v.y);       ho.y = pack_bf2(v.z, v.w);
    lo.x = pack_bf2(v.x - hx, v.y - hy); lo.y = pack_bf2(v.z - hz, v.w - hw);
    *(uint2*)(Xh + i * 2) = ho;
    *(uint2*)(Xl + i * 2) = lo;
}

// ---------------- prep: Qh = bf16((codes@Wq^T+bq)@Wk / 16), c = q.bk/16 ----------------
__global__ __launch_bounds__(256)
void prep_q(const float* __restrict__ cat, const float* __restrict__ typ,
            const float* __restrict__ var, const float* __restrict__ sp,
            const float* __restrict__ Wcat, const float* __restrict__ bcat,
            const float* __restrict__ Wtype, const float* __restrict__ btype,
            const float* __restrict__ Wvar, const float* __restrict__ bvar,
            const float* __restrict__ Wsp, const float* __restrict__ bsp,
            const float* __restrict__ Wk, const float* __restrict__ bk,
            __nv_bfloat16* __restrict__ Qh, float* __restrict__ cvec)
{
    int m = blockIdx.x;
    const float* codes; const float* Wq; const float* bq;
    if (m < 16)       { codes = cat + m * DIM;         Wq = Wcat;  bq = bcat; }
    else if (m < 144) { codes = typ + (m - 16) * DIM;  Wq = Wtype; bq = btype; }
    else if (m < 656) { codes = var + (m - 144) * DIM; Wq = Wvar;  bq = bvar; }
    else              { codes = sp + (m - 656) * DIM;  Wq = Wsp;   bq = bsp; }

    __shared__ float cs[DIM], qs[DIM], red[256];
    int t = threadIdx.x;
    cs[t] = codes[t];
    __syncthreads();

    int w = t >> 5, l = t & 31;
    for (int j = w; j < DIM; j += 8) {
        const float* wr = Wq + j * DIM;
        float s = 0.f;
        #pragma unroll
        for (int i = 0; i < 8; i++) s += wr[l + 32 * i] * cs[l + 32 * i];
        #pragma unroll
        for (int o = 16; o > 0; o >>= 1) s += __shfl_xor_sync(0xffffffffu, s, o);
        if (l == 0) qs[j] = s + bq[j];
    }
    __syncthreads();

    float a = 0.f;
    for (int j = 0; j < DIM; j++) a += qs[j] * Wk[j * DIM + t];
    Qh[m * DIM + t] = __float2bfloat16(a * 0.0625f);

    red[t] = qs[t] * bk[t];
    __syncthreads();
    for (int s = 128; s > 0; s >>= 1) { if (t < s) red[t] += red[t + s]; __syncthreads(); }
    if (t == 0) cvec[m] = red[0] * 0.0625f;
}

// ---------------- logits+exp: E = exp(clip(Qh.Xh + c)), rowsum via atomics ----------------
__global__ __launch_bounds__(256)
void logits_mma(const __nv_bfloat16* __restrict__ Qh,
                const __nv_bfloat16* __restrict__ Xh,
                __nv_bfloat16* __restrict__ Eh,
                __nv_bfloat16* __restrict__ El,
                float* __restrict__ rowsum,
                const float* __restrict__ cvec,
                const unsigned char* __restrict__ mask)
{
    const int SK = 40;
    __shared__ __nv_bfloat16 sA[128 * SK];
    __shared__ __nv_bfloat16 sB[128 * SK];

    int b = blockIdx.z;
    int m0 = blockIdx.y * 128, n0 = blockIdx.x * 128;
    const __nv_bfloat16* Xb = Xh + (long)b * NTOK * DIM;
    int t = threadIdx.x, lane = t & 31, w = t >> 5;
    int wm = (w >> 2) * 64, wn = (w & 3) * 32;

    uint4 ra[2], rb[2];
    auto gload = [&](int kt) {
        #pragma unroll
        for (int i = 0; i < 2; i++) {
            int c = t + i * 256;
            int row = c >> 2, kc = (c & 3) * 8;
            int gm = m0 + row;
            ra[i] = make_uint4(0u, 0u, 0u, 0u);
            if (gm < M_TOT) ra[i] = *(const uint4*)(Qh + gm * DIM + kt * 32 + kc);
            rb[i] = *(const uint4*)(Xb + (long)(n0 + row) * DIM + kt * 32 + kc);
        }
    };
    auto sstore = [&]() {
        #pragma unroll
        for (int i = 0; i < 2; i++) {
            int c = t + i * 256;
            int row = c >> 2, kc = (c & 3) * 8;
            *(uint4*)(sA + row * SK + kc) = ra[i];
            *(uint4*)(sB + row * SK + kc) = rb[i];
        }
    };

    int l15 = lane & 15;
    unsigned aBase = sm_u32(sA + (wm + l15) * SK + (lane >> 4) * 8);
    unsigned bBase = sm_u32(sB + (wn + (l15 & 7)) * SK + (l15 >> 3) * 8);

    float acc[4][4][4] = {};
    gload(0);
    for (int kt = 0; kt < 8; kt++) {
        __syncthreads();
        sstore();
        __syncthreads();
        if (kt < 7) gload(kt + 1);
        #pragma unroll
        for (int ks = 0; ks < 2; ks++) {
            unsigned a[4][4], bf[4][2];
            #pragma unroll
            for (int mi = 0; mi < 4; mi++) ldsm4(a[mi], aBase + (unsigned)(mi * 16 * SK + ks * 16) * 2u);
            #pragma unroll
            for (int ni = 0; ni < 4; ni++) ldsm2(bf[ni], bBase + (unsigned)(ni * 8 * SK + ks * 16) * 2u);
            #pragma unroll
            for (int mi = 0; mi < 4; mi++)
                #pragma unroll
                for (int ni = 0; ni < 4; ni++) mma16816(acc[mi][ni], a[mi], bf[ni]);
        }
    }

    const unsigned char* mrow = mask + (long)b * NTOK;
    int t4 = lane & 3;
    #pragma unroll
    for (int mi = 0; mi < 4; mi++) {
        #pragma unroll
        for (int r = 0; r < 2; r++) {
            int gm = m0 + wm + mi * 16 + (lane >> 2) + r * 8;
            if (gm >= M_TOT) continue;
            float cv = cvec[gm];
            long roff = ((long)b * M_TOT + gm) * NTOK;
            float rs = 0.f;
            #pragma unroll
            for (int ni = 0; ni < 4; ni++) {
                int col = n0 + wn + ni * 8 + t4 * 2;
                float x0 = acc[mi][ni][r * 2 + 0] + cv;
                float x1 = acc[mi][ni][r * 2 + 1] + cv;
                x0 = fminf(fmaxf(x0, -50.f), 50.f);
                x1 = fminf(fmaxf(x1, -50.f), 50.f);
                if (!mrow[col])     x0 = -50.f;
                if (!mrow[col + 1]) x1 = -50.f;
                float e0 = expf(x0);
                float e1 = expf(x1);
                rs += e0 + e1;
                __nv_bfloat162 h, l;
                h.x = __float2bfloat16(e0); h.y = __float2bfloat16(e1);
                l.x = __float2bfloat16(e0 - __bfloat162float(h.x));
                l.y = __float2bfloat16(e1 - __bfloat162float(h.y));
                *(__nv_bfloat162*)(Eh + roff + col) = h;
                *(__nv_bfloat162*)(El + roff + col) = l;
            }
            rs += __shfl_xor_sync(0xffffffffu, rs, 1);
            rs += __shfl_xor_sync(0xffffffffu, rs, 2);
            if (t4 == 0) atomicAdd(&rowsum[b * M_TOT + gm], rs);
        }
    }
}

// ---------------- H = (E @ X) / rowsum  (split-3 bf16, 64x256 block) ----------------
__global__ __launch_bounds__(256)
void h_mma(const __nv_bfloat16* __restrict__ Eh, const __nv_bfloat16* __restrict__ El,
           const __nv_bfloat16* __restrict__ Xh, const __nv_bfloat16* __restrict__ Xl,
           const float* __restrict__ rowsum, float* __restrict__ H)
{
    const int SK = 40, SN = 264;
    __shared__ __nv_bfloat16 sAh[64 * SK];
    __shared__ __nv_bfloat16 sAl[64 * SK];
    __shared__ __nv_bfloat16 sBh[32 * SN];
    __shared__ __nv_bfloat16 sBl[32 * SN];

    int b = blockIdx.z;
    int m0 = blockIdx.y * 64;
    const __nv_bfloat16* Ehb = Eh + (long)b * M_TOT * NTOK;
    const __nv_bfloat16* Elb = El + (long)b * M_TOT * NTOK;
    const __nv_bfloat16* Xhb = Xh + (long)b * NTOK * DIM;
    const __nv_bfloat16* Xlb = Xl + (long)b * NTOK * DIM;
    int t = threadIdx.x, lane = t & 31, w = t >> 5;
    int wm = (w >> 2) * 32, wd = (w & 3) * 64;

    uint4 rah, ral, rbh[4], rbl[4];
    auto gload = [&](int kt) {
        {
            int row = t >> 2, kc = (t & 3) * 8;
            int gm = m0 + row;
            rah = make_uint4(0u, 0u, 0u, 0u);
            ral = rah;
            if (gm < M_TOT) {
                long off = (long)gm * NTOK + kt * 32 + kc;
                rah = *(const uint4*)(Ehb + off);
                ral = *(const uint4*)(Elb + off);
            }
        }
        #pragma unroll
        for (int i = 0; i < 4; i++) {
            int c = t + i * 256;
            int kr = c >> 5, nc = (c & 31) * 8;
            long off = (long)(kt * 32 + kr) * DIM + nc;
            rbh[i] = *(const uint4*)(Xhb + off);
            rbl[i] = *(const uint4*)(Xlb + off);
        }
    };
    auto sstore = [&]() {
        {
            int row = t >> 2, kc = (t & 3) * 8;
            *(uint4*)(sAh + row * SK + kc) = rah;
            *(uint4*)(sAl + row * SK + kc) = ral;
        }
        #pragma unroll
        for (int i = 0; i < 4; i++) {
            int c = t + i * 256;
            int kr = c >> 5, nc = (c & 31) * 8;
            *(uint4*)(sBh + kr * SN + nc) = rbh[i];
            *(uint4*)(sBl + kr * SN + nc) = rbl[i];
        }
    };

    int l15 = lane & 15;
    unsigned ahB = sm_u32(sAh + (wm + l15) * SK + (lane >> 4) * 8);
    unsigned alB = sm_u32(sAl + (wm + l15) * SK + (lane >> 4) * 8);
    unsigned bhB = sm_u32(sBh + l15 * SN + wd);
    unsigned blB = sm_u32(sBl + l15 * SN + wd);

    float acc[2][8][4] = {};
    gload(0);
    for (int kt = 0; kt < NTOK / 32; kt++) {
        __syncthreads();
        sstore();
        __syncthreads();
        if (kt < NTOK / 32 - 1) gload(kt + 1);
        #pragma unroll
        for (int ks = 0; ks < 2; ks++) {
            unsigned ah[2][4], al[2][4];
            ldsm4(ah[0], ahB + (unsigned)(0 * 16 * SK + ks * 16) * 2u);
            ldsm4(ah[1], ahB + (unsigned)(1 * 16 * SK + ks * 16) * 2u);
            ldsm4(al[0], alB + (unsigned)(0 * 16 * SK + ks * 16) * 2u);
            ldsm4(al[1], alB + (unsigned)(1 * 16 * SK + ks * 16) * 2u);
            #pragma unroll
            for (int nj = 0; nj < 8; nj++) {
                unsigned bh[2], bl[2];
                ldsm2t(bh, bhB + (unsigned)(ks * 16 * SN) * 2u + (unsigned)nj * 16u);
                ldsm2t(bl, blB + (unsigned)(ks * 16 * SN) * 2u + (unsigned)nj * 16u);
                mma16816(acc[0][nj], ah[0], bh);
                mma16816(acc[1][nj], ah[1], bh);
                mma16816(acc[0][nj], ah[0], bl);
                mma16816(acc[1][nj], ah[1], bl);
                mma16816(acc[0][nj], al[0], bh);
                mma16816(acc[1][nj], al[1], bh);
            }
        }
    }

    int g = lane >> 2, t4 = lane & 3;
    #pragma unroll
    for (int mi = 0; mi < 2; mi++) {
        #pragma unroll
        for (int r = 0; r < 2; r++) {
            int gm = m0 + wm + mi * 16 + g + r * 8;
            if (gm >= M_TOT) continue;
            float inv = 1.f / rowsum[b * M_TOT + gm];
            float* hrow = H + ((long)b * M_TOT + gm) * DIM;
            #pragma unroll
            for (int nj = 0; nj < 8; nj++) {
                int col = wd + nj * 8 + t4 * 2;
                *(float2*)(hrow + col) =
                    make_float2(acc[mi][nj][r * 2 + 0] * inv,
                                acc[mi][nj][r * 2 + 1] * inv);
            }
        }
    }
}

// ---------------- row norms: sw[b][m] = ||H[b,m]|| / tau ----------------
__global__ __launch_bounds__(256)
void norms_kernel(const float* __restrict__ H, const float* __restrict__ log_tau,
                  float* __restrict__ sw)
{
    int b = blockIdx.y;
    int m = blockIdx.x * 8 + (threadIdx.x >> 5);
    int l = threadIdx.x & 31;
    float tau = fminf(fmaxf(expf(log_tau[0]) + 0.1f, 0.1f), 2.0f);
    const float* hr = H + ((long)b * M_TOT + m) * DIM;
    float s = 0.f;
    #pragma unroll
    for (int i = 0; i < 8; i++) { float x = hr[l + 32 * i]; s += x * x; }
    #pragma unroll
    for (int o = 16; o > 0; o >>= 1) s += __shfl_xor_sync(0xffffffffu, s, o);
    if (l == 0) sw[b * M_TOT + m] = sqrtf(s) / tau;
}

// ---------------- per-batch tail ----------------
__device__ __forceinline__ float blk_sum(float v, float* red, int t)
{
    __syncthreads();
    red[t] = v; __syncthreads();
    for (int s = 128; s > 0; s >>= 1) { if (t < s) red[t] += red[t + s]; __syncthreads(); }
    float r = red[0]; __syncthreads();
    return r;
}
__device__ __forceinline__ float blk_max(float v, float* red, int t)
{
    __syncthreads();
    red[t] = v; __syncthreads();
    for (int s = 128; s > 0; s >>= 1) { if (t < s) red[t] = fmaxf(red[t], red[t + s]); __syncthreads(); }
    float r = red[0]; __syncthreads();
    return r;
}
__device__ void softmax_sparsify(float* a, int len, float thr, float* red, int t)
{
    float m = -1e30f;
    for (int i = t; i < len; i += 256) m = fmaxf(m, a[i]);
    m = blk_max(m, red, t);
    float s = 0.f;
    for (int i = t; i < len; i += 256) { float e = expf(a[i] - m); a[i] = e; s += e; }
    s = blk_sum(s, red, t);
    float inv = 1.f / s;
    float s2 = 0.f;
    for (int i = t; i < len; i += 256) { float p = a[i] * inv; p = (p > thr) ? p : 0.f; a[i] = p; s2 += p; }
    s2 = blk_sum(s2, red, t);
    float inv2 = 1.f / (s2 + 1e-8f);
    for (int i = t; i < len; i += 256) a[i] *= inv2;
    __syncthreads();
}

__global__ __launch_bounds__(256)
void final_kernel(const float* __restrict__ H, const float* __restrict__ swg,
                  const float* __restrict__ part,
                  const float* __restrict__ cnt,
                  const float* __restrict__ Wg1, const float* __restrict__ bg1,
                  const float* __restrict__ Wg2, const float* __restrict__ bg2,
                  const float* __restrict__ Wo,  const float* __restrict__ bo,
                  const float* __restrict__ ln_g, const float* __restrict__ ln_b,
                  const float* __restrict__ lvlw, float* __restrict__ out)
{
    __shared__ float red[256];
    __shared__ float wcs[16], wts[128], wvs[512], wss[16];
    __shared__ float coeff[M_TOT];
    __shared__ float xc[512];
    __shared__ float hb[256], gb[256], yb[256], zg[256];
    __shared__ float lw[4];

    int b = blockIdx.x;
    int t = threadIdx.x;
    const float* Hb = H + (long)b * M_TOT * DIM;
    const float* sw = swg + b * M_TOT;

    if (t == 0) {
        float m = fmaxf(fmaxf(lvlw[0], lvlw[1]), fmaxf(lvlw[2], lvlw[3]));
        float e0 = expf(lvlw[0]-m), e1 = expf(lvlw[1]-m), e2 = expf(lvlw[2]-m), e3 = expf(lvlw[3]-m);
        float s = e0+e1+e2+e3;
        lw[0]=e0/s; lw[1]=e1/s; lw[2]=e2/s; lw[3]=e3/s;
    }

    if (t < 16) wcs[t] = sw[t];
    __syncthreads();
    softmax_sparsify(wcs, 16, 0.1f, red, t);
    if (t < 128) wts[t] = sw[16 + t] * wcs[t >> 3];
    __syncthreads();
    softmax_sparsify(wts, 128, 0.05f, red, t);
    for (int i = t; i < 512; i += 256) wvs[i] = sw[144 + i] * wts[i >> 2];
    __syncthreads();
    softmax_sparsify(wvs, 512, 0.025f, red, t);
    if (t < 16) wss[t] = sw[656 + t];
    __syncthreads();
    softmax_sparsify(wss, 16, 0.1f, red, t);

    for (int i = t; i < M_TOT; i += 256) {
        float c;
        if (i < 16)       c = lw[0] * wcs[i];
        else if (i < 144) c = lw[1] * wts[i - 16];
        else if (i < 656) c = lw[2] * wvs[i - 144];
        else              c = lw[3] * wss[i - 656];
        coeff[i] = c;
    }
    __syncthreads();

    // z[d] = sum_m coeff[m] * H[m][d]  -- 8 independent accumulators
    {
        float z0 = 0.f, z1 = 0.f, z2 = 0.f, z3 = 0.f;
        float z4 = 0.f, z5 = 0.f, z6 = 0.f, z7 = 0.f;
        #pragma unroll 2
        for (int m = 0; m < M_TOT; m += 8) {
            z0 += coeff[m]     * Hb[(m)     * DIM + t];
            z1 += coeff[m + 1] * Hb[(m + 1) * DIM + t];
            z2 += coeff[m + 2] * Hb[(m + 2) * DIM + t];
            z3 += coeff[m + 3] * Hb[(m + 3) * DIM + t];
            z4 += coeff[m + 4] * Hb[(m + 4) * DIM + t];
            z5 += coeff[m + 5] * Hb[(m + 5) * DIM + t];
            z6 += coeff[m + 6] * Hb[(m + 6) * DIM + t];
            z7 += coeff[m + 7] * Hb[(m + 7) * DIM + t];
        }
        xc[t] = ((z0 + z1) + (z2 + z3)) + ((z4 + z5) + (z6 + z7));
    }

    float pp = 0.f, cc = 0.f;
    #pragma unroll
    for (int s = 0; s < 16; s++) {
        pp += part[((long)b * 16 + s) * DIM + t];
        cc += cnt[b * 16 + s];
    }
    xc[256 + t] = pp / (cc + 1e-8f);
    __syncthreads();

    int w = t >> 5, l = t & 31;
    for (int j = w; j < 256; j += 8) {
        const float* wr = Wg1 + j * 512;
        float s = 0.f;
        #pragma unroll
        for (int i = 0; i < 16; i++) s += wr[l + 32 * i] * xc[l + 32 * i];
        #pragma unroll
        for (int o = 16; o > 0; o >>= 1) s += __shfl_xor_sync(0xffffffffu, s, o);
        if (l == 0) {
            float x = s + bg1[j];
            hb[j] = 0.5f * x * (1.0f + erff(x * 0.70710678118654752f));
        }
    }
    __syncthreads();

    for (int j = w; j < 256; j += 8) {
        const float* wr = Wg2 + j * 256;
        float s = 0.f;
        #pragma unroll
        for (int i = 0; i < 8; i++) s += wr[l + 32 * i] * hb[l + 32 * i];
        #pragma unroll
        for (int o = 16; o > 0; o >>= 1) s += __shfl_xor_sync(0xffffffffu, s, o);
        if (l == 0) gb[j] = 1.0f / (1.0f + expf(-(s + bg2[j])));
    }
    __syncthreads();

    zg[t] = xc[t] * gb[t];
    __syncthreads();

    for (int j = w; j < 256; j += 8) {
        const float* wr = Wo + j * 256;
        float s = 0.f;
        #pragma unroll
        for (int i = 0; i < 8; i++) s += wr[l + 32 * i] * zg[l + 32 * i];
        #pragma unroll
        for (int o = 16; o > 0; o >>= 1) s += __shfl_xor_sync(0xffffffffu, s, o);
        if (l == 0) yb[j] = s + bo[j];
    }
    __syncthreads();

    float y = yb[t];
    float mu = blk_sum(y, red, t) * (1.0f / 256.0f);
    float d0 = y - mu;
    float var = blk_sum(d0 * d0, red, t) * (1.0f / 256.0f);
    out[(long)b * DIM + t] = d0 * rsqrtf(var + 1e-5f) * ln_g[t] + ln_b[t];
}

// ---------------- masked position pooling partials ----------------
__global__ __launch_bounds__(256)
void pospool_partial(const float* __restrict__ pos, const unsigned char* __restrict__ mask,
                     float* __restrict__ part, float* __restrict__ cnt)
{
    int s = blockIdx.x, b = blockIdx.y;
    int t = threadIdx.x;
    const float* P = pos + ((long)b * NTOK + s * 256) * DIM;
    const unsigned char* M = mask + (long)b * NTOK + s * 256;
    float acc = 0.f, c = 0.f;
    for (int n = 0; n < 256; n++) {
        float mm = M[n] ? 1.f : 0.f;
        c += mm;
        acc += mm * P[(long)n * DIM + t];
    }
    part[((long)b * 16 + s) * DIM + t] = acc;
    if (t == 0) cnt[b * 16 + s] = c;
}

// ---------------- launch ----------------
extern "C" void kernel_launch(void* const* d_in, const int* in_sizes, int n_in,
                              void* d_out, int out_size)
{
    const float* X    = (const float*)d_in[0];
    const float* pos  = (const float*)d_in[1];
    const unsigned char* mask = (const unsigned char*)d_in[2];
    const float* cat  = (const float*)d_in[3];
    const float* typ  = (const float*)d_in[4];
    const float* var  = (const float*)d_in[5];
    const float* sp   = (const float*)d_in[6];
    const float* log_tau = (const float*)d_in[7];
    const float* Wk   = (const float*)d_in[8];
    const float* bk   = (const float*)d_in[9];
    const float* Wcat = (const float*)d_in[10];
    const float* bcat = (const float*)d_in[11];
    const float* Wtype= (const float*)d_in[12];
    const float* btype= (const float*)d_in[13];
    const float* Wvar = (const float*)d_in[14];
    const float* bvar = (const float*)d_in[15];
    const float* Wsp  = (const float*)d_in[16];
    const float* bsp  = (const float*)d_in[17];
    const float* Wg1  = (const float*)d_in[18];
    const float* bg1  = (const float*)d_in[19];
    const float* Wg2  = (const float*)d_in[20];
    const float* bg2  = (const float*)d_in[21];
    const float* Wo   = (const float*)d_in[22];
    const float* bo   = (const float*)d_in[23];
    const float* ln_g = (const float*)d_in[24];
    const float* ln_b = (const float*)d_in[25];
    const float* lvlw = (const float*)d_in[26];
    float* out = (float*)d_out;

    __nv_bfloat16 *Qh, *Eh, *El, *Xh, *Xl;
    float *cvec, *rs, *H, *sw, *part, *cnt;
    cudaGetSymbolAddress((void**)&Qh,   g_Qh);
    cudaGetSymbolAddress((void**)&cvec, g_c);
    cudaGetSymbolAddress((void**)&Eh,   g_Eh);
    cudaGetSymbolAddress((void**)&El,   g_El);
    cudaGetSymbolAddress((void**)&Xh,   g_Xh);
    cudaGetSymbolAddress((void**)&Xl,   g_Xl);
    cudaGetSymbolAddress((void**)&rs,   g_rs);
    cudaGetSymbolAddress((void**)&H,    g_H);
    cudaGetSymbolAddress((void**)&sw,   g_sw);
    cudaGetSymbolAddress((void**)&part, g_part);
    cudaGetSymbolAddress((void**)&cnt,  g_cnt);

    // 1) X -> hi/lo bf16
    {
        long n4 = (long)BATCH * NTOK * DIM / 4;
        convert_x<<<(unsigned)(n4 / 256), 256>>>((const float4*)X,
                                                 (unsigned*)Xh, (unsigned*)Xl);
    }

    // 2) Q' and c ; zero rowsums
    prep_q<<<M_TOT, 256>>>(cat, typ, var, sp, Wcat, bcat, Wtype, btype,
                           Wvar, bvar, Wsp, bsp, Wk, bk, Qh, cvec);
    rs_zero<<<(BATCH * M_TOT) / 256, 256>>>(rs);

    // 3) logits -> exp (bf16 hi/lo) + row sums
    {
        dim3 grid(NTOK / 128, (M_TOT + 127) / 128, BATCH);
        logits_mma<<<grid, 256>>>(Qh, Xh, Eh, El, rs, cvec, mask);
    }

    // 4) H = (E @ X) / rowsum (split-3 bf16, 64x256 blocks)
    {
        dim3 grid(1, (M_TOT + 63) / 64, BATCH);
        h_mma<<<grid, 256>>>(Eh, El, Xh, Xl, rs, H);
    }

    // 5) position pooling partials
    {
        dim3 grid(16, BATCH);
        pospool_partial<<<grid, 256>>>(pos, mask, part, cnt);
    }

    // 6) row norms (full-chip parallel)
    {
        dim3 grid(M_TOT / 8, BATCH);
        norms_kernel<<<grid, 256>>>(H, log_tau, sw);
    }

    // 7) per-batch tail
    final_kernel<<<BATCH, 256>>>(H, sw, part, cnt,
                                 Wg1, bg1, Wg2, bg2, Wo, bo,
                                 ln_g, ln_b, lvlw, out);
}

// round 8
// speedup vs baseline: 1.5742x; 1.0432x over previous
#include <cuda_runtime.h>
#include <cuda_bf16.h>
#include <math.h>

#define BATCH 32
#define NTOK  4096
#define DIM   256
#define M_TOT 672
#define MPAD  768

// ---------------- scratch (M padded to 768; pad rows are zero/garbage, never read) ----------------
__device__ __nv_bfloat16 g_Qh[MPAD * DIM];
__device__ float         g_c [MPAD];
__device__ __nv_bfloat16 g_Eh[(long)BATCH * MPAD * NTOK];
__device__ __nv_bfloat16 g_El[(long)BATCH * MPAD * NTOK];
__device__ __nv_bfloat16 g_Xh[(long)BATCH * NTOK * DIM];
__device__ __nv_bfloat16 g_Xl[(long)BATCH * NTOK * DIM];
__device__ float g_rs[BATCH * MPAD];
__device__ float g_H[(long)BATCH * MPAD * DIM];
__device__ float g_sw[BATCH * M_TOT];
__device__ float g_part[BATCH * 16 * DIM];
__device__ float g_cnt [BATCH * 16];

// ---------------- helpers ----------------
__device__ __forceinline__ unsigned sm_u32(const void* p) {
    return (unsigned)__cvta_generic_to_shared(p);
}
__device__ __forceinline__ void cpa16(unsigned s, const void* g) {
    asm volatile("cp.async.cg.shared.global [%0], [%1], 16;" :: "r"(s), "l"(g));
}
__device__ __forceinline__ void cpa_commit() { asm volatile("cp.async.commit_group;"); }
template<int N> __device__ __forceinline__ void cpa_wait() {
    asm volatile("cp.async.wait_group %0;" :: "n"(N));
}
__device__ __forceinline__ void ldsm4(unsigned r[4], unsigned addr) {
    asm volatile("ldmatrix.sync.aligned.m8n8.x4.shared.b16 {%0,%1,%2,%3},[%4];"
                 : "=r"(r[0]), "=r"(r[1]), "=r"(r[2]), "=r"(r[3]) : "r"(addr));
}
__device__ __forceinline__ void ldsm2(unsigned r[2], unsigned addr) {
    asm volatile("ldmatrix.sync.aligned.m8n8.x2.shared.b16 {%0,%1},[%2];"
                 : "=r"(r[0]), "=r"(r[1]) : "r"(addr));
}
__device__ __forceinline__ void ldsm2t(unsigned r[2], unsigned addr) {
    asm volatile("ldmatrix.sync.aligned.m8n8.x2.trans.shared.b16 {%0,%1},[%2];"
                 : "=r"(r[0]), "=r"(r[1]) : "r"(addr));
}
__device__ __forceinline__ void mma16816(float c[4], const unsigned a[4], const unsigned b[2]) {
    asm volatile(
        "mma.sync.aligned.m16n8k16.row.col.f32.bf16.bf16.f32 "
        "{%0,%1,%2,%3},{%4,%5,%6,%7},{%8,%9},{%0,%1,%2,%3};"
        : "+f"(c[0]), "+f"(c[1]), "+f"(c[2]), "+f"(c[3])
        : "r"(a[0]), "r"(a[1]), "r"(a[2]), "r"(a[3]), "r"(b[0]), "r"(b[1]));
}
__device__ __forceinline__ unsigned pack_bf2(float a, float b) {
    __nv_bfloat162 t;
    t.x = __float2bfloat16(a); t.y = __float2bfloat16(b);
    return *(unsigned*)&t;
}

// ---------------- zero rowsums ----------------
__global__ __launch_bounds__(256)
void rs_zero(float* __restrict__ rs)
{
    rs[blockIdx.x * 256 + threadIdx.x] = 0.f;
}

// ---------------- X -> hi/lo bf16 ----------------
__global__ __launch_bounds__(256)
void convert_x(const float4* __restrict__ X, unsigned* __restrict__ Xh,
               unsigned* __restrict__ Xl)
{
    long i = (long)blockIdx.x * 256 + threadIdx.x;
    float4 v = X[i];
    float hx = __bfloat162float(__float2bfloat16(v.x));
    float hy = __bfloat162float(__float2bfloat16(v.y));
    float hz = __bfloat162float(__float2bfloat16(v.z));
    float hw = __bfloat162float(__float2bfloat16(v.w));
    uint2 ho, lo;
    ho.x = pack_bf2(v.x, v.y);           ho.y = pack_bf2(v.z, v.w);
    lo.x = pack_bf2(v.x - hx, v.y - hy); lo.y = pack_bf2(v.z - hz, v.w - hw);
    *(uint2*)(Xh + i * 2) = ho;
    *(uint2*)(Xl + i * 2) = lo;
}

// ---------------- prep: Qh = bf16((codes@Wq^T+bq)@Wk / 16), c = q.bk/16 ----------------
__global__ __launch_bounds__(256)
void prep_q(const float* __restrict__ cat, const float* __restrict__ typ,
            const float* __restrict__ var, const float* __restrict__ sp,
            const float* __restrict__ Wcat, const float* __restrict__ bcat,
            const float* __restrict__ Wtype, const float* __restrict__ btype,
            const float* __restrict__ Wvar, const float* __restrict__ bvar,
            const float* __restrict__ Wsp, const float* __restrict__ bsp,
            const float* __restrict__ Wk, const float* __restrict__ bk,
            __nv_bfloat16* __restrict__ Qh, float* __restrict__ cvec)
{
    int m = blockIdx.x;
    const float* codes; const float* Wq; const float* bq;
    if (m < 16)       { codes = cat + m * DIM;         Wq = Wcat;  bq = bcat; }
    else if (m < 144) { codes = typ + (m - 16) * DIM;  Wq = Wtype; bq = btype; }
    else if (m < 656) { codes = var + (m - 144) * DIM; Wq = Wvar;  bq = bvar; }
    else              { codes = sp + (m - 656) * DIM;  Wq = Wsp;   bq = bsp; }

    __shared__ float cs[DIM], qs[DIM], red[256];
    int t = threadIdx.x;
    cs[t] = codes[t];
    __syncthreads();

    int w = t >> 5, l = t & 31;
    for (int j = w; j < DIM; j += 8) {
        const float* wr = Wq + j * DIM;
        float s = 0.f;
        #pragma unroll
        for (int i = 0; i < 8; i++) s += wr[l + 32 * i] * cs[l + 32 * i];
        #pragma unroll
        for (int o = 16; o > 0; o >>= 1) s += __shfl_xor_sync(0xffffffffu, s, o);
        if (l == 0) qs[j] = s + bq[j];
    }
    __syncthreads();

    float a = 0.f;
    for (int j = 0; j < DIM; j++) a += qs[j] * Wk[j * DIM + t];
    Qh[m * DIM + t] = __float2bfloat16(a * 0.0625f);

    red[t] = qs[t] * bk[t];
    __syncthreads();
    for (int s = 128; s > 0; s >>= 1) { if (t < s) red[t] += red[t + s]; __syncthreads(); }
    if (t == 0) cvec[m] = red[0] * 0.0625f;
}

// ---------------- logits+exp: E = exp(clip(Qh.Xh + c)), rowsum atomics ----------------
// 2-stage cp.async pipeline; epilogue staged through smem for coalesced stores.
extern __shared__ char dsm[];

__global__ __launch_bounds__(256)
void logits_mma(const __nv_bfloat16* __restrict__ Qh,
                const __nv_bfloat16* __restrict__ Xh,
                __nv_bfloat16* __restrict__ Eh,
                __nv_bfloat16* __restrict__ El,
                float* __restrict__ rowsum,
                const float* __restrict__ cvec,
                const unsigned char* __restrict__ mask)
{
    const int SK = 40;                 // smem row stride (halves)
    const int STAGE = 20480;           // bytes per stage: (128*40)*2 * 2 tiles
    const int SE = 136;                // epilogue staging stride (halves)

    int b = blockIdx.z;
    int m0 = blockIdx.y * 128, n0 = blockIdx.x * 128;
    const __nv_bfloat16* Xb = Xh + (long)b * NTOK * DIM;
    int t = threadIdx.x, lane = t & 31, w = t >> 5;
    int wm = (w >> 2) * 64, wn = (w & 3) * 32;
    int l15 = lane & 15, t4 = lane & 3;

    auto load_stage = [&](int kt, int s) {
        char* base = dsm + s * STAGE;
        #pragma unroll
        for (int i = 0; i < 2; i++) {
            int c = t + i * 256;
            int row = c >> 2, kq = c & 3;
            cpa16(sm_u32(base + (row * SK + kq * 8) * 2),
                  Qh + (m0 + row) * DIM + kt * 32 + kq * 8);
            cpa16(sm_u32(base + 10240 + (row * SK + kq * 8) * 2),
                  Xb + (long)(n0 + row) * DIM + kt * 32 + kq * 8);
        }
        cpa_commit();
    };

    float acc[4][4][4] = {};
    load_stage(0, 0);
    for (int kt = 0; kt < 8; kt++) {
        cpa_wait<0>();
        __syncthreads();
        if (kt < 7) load_stage(kt + 1, (kt + 1) & 1);
        char* base = dsm + (kt & 1) * STAGE;
        unsigned aBase = sm_u32(base + ((wm + l15) * SK + (lane >> 4) * 8) * 2);
        unsigned bBase = sm_u32(base + 10240 + ((wn + (l15 & 7)) * SK + (l15 >> 3) * 8) * 2);
        #pragma unroll
        for (int ks = 0; ks < 2; ks++) {
            unsigned a[4][4], bf[4][2];
            #pragma unroll
            for (int mi = 0; mi < 4; mi++) ldsm4(a[mi], aBase + (unsigned)(mi * 16 * SK + ks * 16) * 2u);
            #pragma unroll
            for (int ni = 0; ni < 4; ni++) ldsm2(bf[ni], bBase + (unsigned)(ni * 8 * SK + ks * 16) * 2u);
            #pragma unroll
            for (int mi = 0; mi < 4; mi++)
                #pragma unroll
                for (int ni = 0; ni < 4; ni++) mma16816(acc[mi][ni], a[mi], bf[ni]);
        }
    }
    __syncthreads();   // smem reuse for epilogue staging

    __nv_bfloat16* sEh = (__nv_bfloat16*)dsm;
    __nv_bfloat16* sEl = (__nv_bfloat16*)(dsm + 34816);
    const unsigned char* mrow = mask + (long)b * NTOK + n0;

    #pragma unroll
    for (int mi = 0; mi < 4; mi++) {
        #pragma unroll
        for (int r = 0; r < 2; r++) {
            int row = wm + mi * 16 + (lane >> 2) + r * 8;    // 0..127
            float cv = cvec[m0 + row];
            float rs = 0.f;
            #pragma unroll
            for (int ni = 0; ni < 4; ni++) {
                int col = wn + ni * 8 + t4 * 2;              // 0..127
                float x0 = acc[mi][ni][r * 2 + 0] + cv;
                float x1 = acc[mi][ni][r * 2 + 1] + cv;
                x0 = fminf(fmaxf(x0, -50.f), 50.f);
                x1 = fminf(fmaxf(x1, -50.f), 50.f);
                if (!mrow[col])     x0 = -50.f;
                if (!mrow[col + 1]) x1 = -50.f;
                float e0 = __expf(x0);
                float e1 = __expf(x1);
                rs += e0 + e1;
                __nv_bfloat162 h, l;
                h.x = __float2bfloat16(e0); h.y = __float2bfloat16(e1);
                l.x = __float2bfloat16(e0 - __bfloat162float(h.x));
                l.y = __float2bfloat16(e1 - __bfloat162float(h.y));
                *(__nv_bfloat162*)(sEh + row * SE + col) = h;
                *(__nv_bfloat162*)(sEl + row * SE + col) = l;
            }
            rs += __shfl_xor_sync(0xffffffffu, rs, 1);
            rs += __shfl_xor_sync(0xffffffffu, rs, 2);
            if (t4 == 0) atomicAdd(&rowsum[b * MPAD + m0 + row], rs);
        }
    }
    __syncthreads();

    long robase = ((long)b * MPAD + m0) * NTOK + n0;
    #pragma unroll
    for (int i = 0; i < 8; i++) {
        int c = t + i * 256;
        int row = c >> 4, seg = c & 15;
        uint4 vh = *(uint4*)(sEh + row * SE + seg * 8);
        uint4 vl = *(uint4*)(sEl + row * SE + seg * 8);
        *(uint4*)(Eh + robase + (long)row * NTOK + seg * 8) = vh;
        *(uint4*)(El + robase + (long)row * NTOK + seg * 8) = vl;
    }
}

// ---------------- H = (E @ X) / rowsum  (split-3 bf16, 64x256 block, cp.async) ----------------
__global__ __launch_bounds__(256)
void h_mma(const __nv_bfloat16* __restrict__ Eh, const __nv_bfloat16* __restrict__ El,
           const __nv_bfloat16* __restrict__ Xh, const __nv_bfloat16* __restrict__ Xl,
           const float* __restrict__ rowsum, float* __restrict__ H)
{
    const int SK = 40, SN = 264;
    // stage layout (halves): Ah @0 (64*40), Al @2560, Bh @5120 (32*264), Bl @13568
    const int STAGE = 44032;   // bytes

    int b = blockIdx.z;
    int m0 = blockIdx.y * 64;
    const __nv_bfloat16* Ehb = Eh + ((long)b * MPAD + m0) * NTOK;
    const __nv_bfloat16* Elb = El + ((long)b * MPAD + m0) * NTOK;
    const __nv_bfloat16* Xhb = Xh + (long)b * NTOK * DIM;
    const __nv_bfloat16* Xlb = Xl + (long)b * NTOK * DIM;
    int t = threadIdx.x, lane = t & 31, w = t >> 5;
    int wm = (w >> 2) * 32, wd = (w & 3) * 64;
    int l15 = lane & 15;

    auto load_stage = [&](int kt, int s) {
        char* base = dsm + s * STAGE;
        {
            int row = t >> 2, kq = t & 3;
            long off = (long)row * NTOK + kt * 32 + kq * 8;
            cpa16(sm_u32(base + (row * SK + kq * 8) * 2), Ehb + off);
            cpa16(sm_u32(base + 5120 + (row * SK + kq * 8) * 2), Elb + off);
        }
        #pragma unroll
        for (int i = 0; i < 4; i++) {
            int c = t + i * 256;
            int kr = c >> 5, nc = (c & 31) * 8;
            long off = (long)(kt * 32 + kr) * DIM + nc;
            cpa16(sm_u32(base + 10240 + (kr * SN + nc) * 2), Xhb + off);
            cpa16(sm_u32(base + 27136 + (kr * SN + nc) * 2), Xlb + off);
        }
        cpa_commit();
    };

    float acc[2][8][4] = {};
    load_stage(0, 0);
    for (int kt = 0; kt < NTOK / 32; kt++) {
        cpa_wait<0>();
        __syncthreads();
        if (kt < NTOK / 32 - 1) load_stage(kt + 1, (kt + 1) & 1);
        char* base = dsm + (kt & 1) * STAGE;
        unsigned ahB = sm_u32(base + ((wm + l15) * SK + (lane >> 4) * 8) * 2);
        unsigned alB = ahB + 5120 * 2;
        unsigned bhB = sm_u32(base + 10240 + (l15 * SN + wd) * 2);
        unsigned blB = bhB + (27136 - 10240);
        #pragma unroll
        for (int ks = 0; ks < 2; ks++) {
            unsigned ah[2][4], al[2][4];
            ldsm4(ah[0], ahB + (unsigned)(0 * 16 * SK + ks * 16) * 2u);
            ldsm4(ah[1], ahB + (unsigned)(1 * 16 * SK + ks * 16) * 2u);
            ldsm4(al[0], alB + (unsigned)(0 * 16 * SK + ks * 16) * 2u);
            ldsm4(al[1], alB + (unsigned)(1 * 16 * SK + ks * 16) * 2u);
            #pragma unroll
            for (int nj = 0; nj < 8; nj++) {
                unsigned bh[2], bl[2];
                ldsm2t(bh, bhB + (unsigned)(ks * 16 * SN) * 2u + (unsigned)nj * 16u);
                ldsm2t(bl, blB + (unsigned)(ks * 16 * SN) * 2u + (unsigned)nj * 16u);
                mma16816(acc[0][nj], ah[0], bh);
                mma16816(acc[1][nj], ah[1], bh);
                mma16816(acc[0][nj], ah[0], bl);
                mma16816(acc[1][nj], ah[1], bl);
                mma16816(acc[0][nj], al[0], bh);
                mma16816(acc[1][nj], al[1], bh);
            }
        }
    }

    int g = lane >> 2, t4 = lane & 3;
    #pragma unroll
    for (int mi = 0; mi < 2; mi++) {
        #pragma unroll
        for (int r = 0; r < 2; r++) {
            int row = wm + mi * 16 + g + r * 8;
            float inv = 1.f / rowsum[b * MPAD + m0 + row];
            float* hrow = H + ((long)b * MPAD + m0 + row) * DIM;
            #pragma unroll
            for (int nj = 0; nj < 8; nj++) {
                int col = wd + nj * 8 + t4 * 2;
                *(float2*)(hrow + col) =
                    make_float2(acc[mi][nj][r * 2 + 0] * inv,
                                acc[mi][nj][r * 2 + 1] * inv);
            }
        }
    }
}

// ---------------- row norms: sw[b][m] = ||H[b,m]|| / tau ----------------
__global__ __launch_bounds__(256)
void norms_kernel(const float* __restrict__ H, const float* __restrict__ log_tau,
                  float* __restrict__ sw)
{
    int b = blockIdx.y;
    int m = blockIdx.x * 8 + (threadIdx.x >> 5);
    int l = threadIdx.x & 31;
    float tau = fminf(fmaxf(expf(log_tau[0]) + 0.1f, 0.1f), 2.0f);
    const float* hr = H + ((long)b * MPAD + m) * DIM;
    float s = 0.f;
    #pragma unroll
    for (int i = 0; i < 8; i++) { float x = hr[l + 32 * i]; s += x * x; }
    #pragma unroll
    for (int o = 16; o > 0; o >>= 1) s += __shfl_xor_sync(0xffffffffu, s, o);
    if (l == 0) sw[b * M_TOT + m] = sqrtf(s) / tau;
}

// ---------------- per-batch tail ----------------
__device__ __forceinline__ float blk_sum(float v, float* red, int t)
{
    __syncthreads();
    red[t] = v; __syncthreads();
    for (int s = 128; s > 0; s >>= 1) { if (t < s) red[t] += red[t + s]; __syncthreads(); }
    float r = red[0]; __syncthreads();
    return r;
}
__device__ __forceinline__ float blk_max(float v, float* red, int t)
{
    __syncthreads();
    red[t] = v; __syncthreads();
    for (int s = 128; s > 0; s >>= 1) { if (t < s) red[t] = fmaxf(red[t], red[t + s]); __syncthreads(); }
    float r = red[0]; __syncthreads();
    return r;
}
__device__ void softmax_sparsify(float* a, int len, float thr, float* red, int t)
{
    float m = -1e30f;
    for (int i = t; i < len; i += 256) m = fmaxf(m, a[i]);
    m = blk_max(m, red, t);
    float s = 0.f;
    for (int i = t; i < len; i += 256) { float e = expf(a[i] - m); a[i] = e; s += e; }
    s = blk_sum(s, red, t);
    float inv = 1.f / s;
    float s2 = 0.f;
    for (int i = t; i < len; i += 256) { float p = a[i] * inv; p = (p > thr) ? p : 0.f; a[i] = p; s2 += p; }
    s2 = blk_sum(s2, red, t);
    float inv2 = 1.f / (s2 + 1e-8f);
    for (int i = t; i < len; i += 256) a[i] *= inv2;
    __syncthreads();
}

__global__ __launch_bounds__(256)
void final_kernel(const float* __restrict__ H, const float* __restrict__ swg,
                  const float* __restrict__ part,
                  const float* __restrict__ cnt,
                  const float* __restrict__ Wg1, const float* __restrict__ bg1,
                  const float* __restrict__ Wg2, const float* __restrict__ bg2,
                  const float* __restrict__ Wo,  const float* __restrict__ bo,
                  const float* __restrict__ ln_g, const float* __restrict__ ln_b,
                  const float* __restrict__ lvlw, float* __restrict__ out)
{
    __shared__ float red[256];
    __shared__ float wcs[16], wts[128], wvs[512], wss[16];
    __shared__ float coeff[M_TOT];
    __shared__ float xc[512];
    __shared__ float hb[256], gb[256], yb[256], zg[256];
    __shared__ float lw[4];

    int b = blockIdx.x;
    int t = threadIdx.x;
    const float* Hb = H + (long)b * MPAD * DIM;
    const float* sw = swg + b * M_TOT;

    if (t == 0) {
        float m = fmaxf(fmaxf(lvlw[0], lvlw[1]), fmaxf(lvlw[2], lvlw[3]));
        float e0 = expf(lvlw[0]-m), e1 = expf(lvlw[1]-m), e2 = expf(lvlw[2]-m), e3 = expf(lvlw[3]-m);
        float s = e0+e1+e2+e3;
        lw[0]=e0/s; lw[1]=e1/s; lw[2]=e2/s; lw[3]=e3/s;
    }

    if (t < 16) wcs[t] = sw[t];
    __syncthreads();
    softmax_sparsify(wcs, 16, 0.1f, red, t);
    if (t < 128) wts[t] = sw[16 + t] * wcs[t >> 3];
    __syncthreads();
    softmax_sparsify(wts, 128, 0.05f, red, t);
    for (int i = t; i < 512; i += 256) wvs[i] = sw[144 + i] * wts[i >> 2];
    __syncthreads();
    softmax_sparsify(wvs, 512, 0.025f, red, t);
    if (t < 16) wss[t] = sw[656 + t];
    __syncthreads();
    softmax_sparsify(wss, 16, 0.1f, red, t);

    for (int i = t; i < M_TOT; i += 256) {
        float c;
        if (i < 16)       c = lw[0] * wcs[i];
        else if (i < 144) c = lw[1] * wts[i - 16];
        else if (i < 656) c = lw[2] * wvs[i - 144];
        else              c = lw[3] * wss[i - 656];
        coeff[i] = c;
    }
    __syncthreads();

    {
        float z0 = 0.f, z1 = 0.f, z2 = 0.f, z3 = 0.f;
        float z4 = 0.f, z5 = 0.f, z6 = 0.f, z7 = 0.f;
        #pragma unroll 2
        for (int m = 0; m < M_TOT; m += 8) {
            z0 += coeff[m]     * Hb[(m)     * DIM + t];
            z1 += coeff[m + 1] * Hb[(m + 1) * DIM + t];
            z2 += coeff[m + 2] * Hb[(m + 2) * DIM + t];
            z3 += coeff[m + 3] * Hb[(m + 3) * DIM + t];
            z4 += coeff[m + 4] * Hb[(m + 4) * DIM + t];
            z5 += coeff[m + 5] * Hb[(m + 5) * DIM + t];
            z6 += coeff[m + 6] * Hb[(m + 6) * DIM + t];
            z7 += coeff[m + 7] * Hb[(m + 7) * DIM + t];
        }
        xc[t] = ((z0 + z1) + (z2 + z3)) + ((z4 + z5) + (z6 + z7));
    }

    float pp = 0.f, cc = 0.f;
    #pragma unroll
    for (int s = 0; s < 16; s++) {
        pp += part[((long)b * 16 + s) * DIM + t];
        cc += cnt[b * 16 + s];
    }
    xc[256 + t] = pp / (cc + 1e-8f);
    __syncthreads();

    int w = t >> 5, l = t & 31;
    for (int j = w; j < 256; j += 8) {
        const float* wr = Wg1 + j * 512;
        float s = 0.f;
        #pragma unroll
        for (int i = 0; i < 16; i++) s += wr[l + 32 * i] * xc[l + 32 * i];
        #pragma unroll
        for (int o = 16; o > 0; o >>= 1) s += __shfl_xor_sync(0xffffffffu, s, o);
        if (l == 0) {
            float x = s + bg1[j];
            hb[j] = 0.5f * x * (1.0f + erff(x * 0.70710678118654752f));
        }
    }
    __syncthreads();

    for (int j = w; j < 256; j += 8) {
        const float* wr = Wg2 + j * 256;
        float s = 0.f;
        #pragma unroll
        for (int i = 0; i < 8; i++) s += wr[l + 32 * i] * hb[l + 32 * i];
        #pragma unroll
        for (int o = 16; o > 0; o >>= 1) s += __shfl_xor_sync(0xffffffffu, s, o);
        if (l == 0) gb[j] = 1.0f / (1.0f + expf(-(s + bg2[j])));
    }
    __syncthreads();

    zg[t] = xc[t] * gb[t];
    __syncthreads();

    for (int j = w; j < 256; j += 8) {
        const float* wr = Wo + j * 256;
        float s = 0.f;
        #pragma unroll
        for (int i = 0; i < 8; i++) s += wr[l + 32 * i] * zg[l + 32 * i];
        #pragma unroll
        for (int o = 16; o > 0; o >>= 1) s += __shfl_xor_sync(0xffffffffu, s, o);
        if (l == 0) yb[j] = s + bo[j];
    }
    __syncthreads();

    float y = yb[t];
    float mu = blk_sum(y, red, t) * (1.0f / 256.0f);
    float d0 = y - mu;
    float var = blk_sum(d0 * d0, red, t) * (1.0f / 256.0f);
    out[(long)b * DIM + t] = d0 * rsqrtf(var + 1e-5f) * ln_g[t] + ln_b[t];
}

// ---------------- masked position pooling partials ----------------
__global__ __launch_bounds__(256)
void pospool_partial(const float* __restrict__ pos, const unsigned char* __restrict__ mask,
                     float* __restrict__ part, float* __restrict__ cnt)
{
    int s = blockIdx.x, b = blockIdx.y;
    int t = threadIdx.x;
    const float* P = pos + ((long)b * NTOK + s * 256) * DIM;
    const unsigned char* M = mask + (long)b * NTOK + s * 256;
    float acc = 0.f, c = 0.f;
    for (int n = 0; n < 256; n++) {
        float mm = M[n] ? 1.f : 0.f;
        c += mm;
        acc += mm * P[(long)n * DIM + t];
    }
    part[((long)b * 16 + s) * DIM + t] = acc;
    if (t == 0) cnt[b * 16 + s] = c;
}

// ---------------- launch ----------------
extern "C" void kernel_launch(void* const* d_in, const int* in_sizes, int n_in,
                              void* d_out, int out_size)
{
    const float* X    = (const float*)d_in[0];
    const float* pos  = (const float*)d_in[1];
    const unsigned char* mask = (const unsigned char*)d_in[2];
    const float* cat  = (const float*)d_in[3];
    const float* typ  = (const float*)d_in[4];
    const float* var  = (const float*)d_in[5];
    const float* sp   = (const float*)d_in[6];
    const float* log_tau = (const float*)d_in[7];
    const float* Wk   = (const float*)d_in[8];
    const float* bk   = (const float*)d_in[9];
    const float* Wcat = (const float*)d_in[10];
    const float* bcat = (const float*)d_in[11];
    const float* Wtype= (const float*)d_in[12];
    const float* btype= (const float*)d_in[13];
    const float* Wvar = (const float*)d_in[14];
    const float* bvar = (const float*)d_in[15];
    const float* Wsp  = (const float*)d_in[16];
    const float* bsp  = (const float*)d_in[17];
    const float* Wg1  = (const float*)d_in[18];
    const float* bg1  = (const float*)d_in[19];
    const float* Wg2  = (const float*)d_in[20];
    const float* bg2  = (const float*)d_in[21];
    const float* Wo   = (const float*)d_in[22];
    const float* bo   = (const float*)d_in[23];
    const float* ln_g = (const float*)d_in[24];
    const float* ln_b = (const float*)d_in[25];
    const float* lvlw = (const float*)d_in[26];
    float* out = (float*)d_out;

    __nv_bfloat16 *Qh, *Eh, *El, *Xh, *Xl;
    float *cvec, *rs, *H, *sw, *part, *cnt;
    cudaGetSymbolAddress((void**)&Qh,   g_Qh);
    cudaGetSymbolAddress((void**)&cvec, g_c);
    cudaGetSymbolAddress((void**)&Eh,   g_Eh);
    cudaGetSymbolAddress((void**)&El,   g_El);
    cudaGetSymbolAddress((void**)&Xh,   g_Xh);
    cudaGetSymbolAddress((void**)&Xl,   g_Xl);
    cudaGetSymbolAddress((void**)&rs,   g_rs);
    cudaGetSymbolAddress((void**)&H,    g_H);
    cudaGetSymbolAddress((void**)&sw,   g_sw);
    cudaGetSymbolAddress((void**)&part, g_part);
    cudaGetSymbolAddress((void**)&cnt,  g_cnt);

    cudaFuncSetAttribute(logits_mma, cudaFuncAttributeMaxDynamicSharedMemorySize, 69632);
    cudaFuncSetAttribute(h_mma,      cudaFuncAttributeMaxDynamicSharedMemorySize, 88064);

    // 1) X -> hi/lo bf16
    {
        long n4 = (long)BATCH * NTOK * DIM / 4;
        convert_x<<<(unsigned)(n4 / 256), 256>>>((const float4*)X,
                                                 (unsigned*)Xh, (unsigned*)Xl);
    }

    // 2) Q' and c ; zero rowsums
    prep_q<<<M_TOT, 256>>>(cat, typ, var, sp, Wcat, bcat, Wtype, btype,
                           Wvar, bvar, Wsp, bsp, Wk, bk, Qh, cvec);
    rs_zero<<<(BATCH * MPAD) / 256, 256>>>(rs);

    // 3) logits -> exp (bf16 hi/lo) + row sums
    {
        dim3 grid(NTOK / 128, MPAD / 128, BATCH);
        logits_mma<<<grid, 256, 69632>>>(Qh, Xh, Eh, El, rs, cvec, mask);
    }

    // 4) H = (E @ X) / rowsum (split-3 bf16, 64x256 blocks)
    {
        dim3 grid(1, 11, BATCH);     // 11*64 = 704 >= 672 rows
        h_mma<<<grid, 256, 88064>>>(Eh, El, Xh, Xl, rs, H);
    }

    // 5) position pooling partials
    {
        dim3 grid(16, BATCH);
        pospool_partial<<<grid, 256>>>(pos, mask, part, cnt);
    }

    // 6) row norms
    {
        dim3 grid(M_TOT / 8, BATCH);
        norms_kernel<<<grid, 256>>>(H, log_tau, sw);
    }

    // 7) per-batch tail
    final_kernel<<<BATCH, 256>>>(H, sw, part, cnt,
                                 Wg1, bg1, Wg2, bg2, Wo, bo,
                                 ln_g, ln_b, lvlw, out);
}

// round 9
// speedup vs baseline: 1.9303x; 1.2262x over previous
#include <cuda_runtime.h>
#include <cuda_bf16.h>
#include <cuda_fp16.h>
#include <math.h>

#define BATCH 32
#define NTOK  4096
#define DIM   256
#define M_TOT 672
#define MPAD  768

// ---------------- scratch ----------------
__device__ __half g_Qh[MPAD * DIM];          // Q' * 64  (i.e. (q@Wk)/16 * 1024)
__device__ float  g_c [MPAD];
__device__ __half g_E [(long)BATCH * MPAD * NTOK];   // exp(logit), fp16
__device__ __half g_Xh[(long)BATCH * NTOK * DIM];    // fp16 hi
__device__ __half g_Xl[(long)BATCH * NTOK * DIM];    // fp16 residual
__device__ float g_rs[BATCH * MPAD];
__device__ float g_H[(long)BATCH * MPAD * DIM];
__device__ float g_sw[BATCH * M_TOT];
__device__ float g_part[BATCH * 16 * DIM];
__device__ float g_cnt [BATCH * 16];

// ---------------- helpers ----------------
__device__ __forceinline__ unsigned sm_u32(const void* p) {
    return (unsigned)__cvta_generic_to_shared(p);
}
__device__ __forceinline__ void cpa16(unsigned s, const void* g) {
    asm volatile("cp.async.cg.shared.global [%0], [%1], 16;" :: "r"(s), "l"(g));
}
__device__ __forceinline__ void cpa_commit() { asm volatile("cp.async.commit_group;"); }
template<int N> __device__ __forceinline__ void cpa_wait() {
    asm volatile("cp.async.wait_group %0;" :: "n"(N));
}
__device__ __forceinline__ void ldsm4(unsigned r[4], unsigned addr) {
    asm volatile("ldmatrix.sync.aligned.m8n8.x4.shared.b16 {%0,%1,%2,%3},[%4];"
                 : "=r"(r[0]), "=r"(r[1]), "=r"(r[2]), "=r"(r[3]) : "r"(addr));
}
__device__ __forceinline__ void ldsm2(unsigned r[2], unsigned addr) {
    asm volatile("ldmatrix.sync.aligned.m8n8.x2.shared.b16 {%0,%1},[%2];"
                 : "=r"(r[0]), "=r"(r[1]) : "r"(addr));
}
__device__ __forceinline__ void ldsm2t(unsigned r[2], unsigned addr) {
    asm volatile("ldmatrix.sync.aligned.m8n8.x2.trans.shared.b16 {%0,%1},[%2];"
                 : "=r"(r[0]), "=r"(r[1]) : "r"(addr));
}
__device__ __forceinline__ void mma16816(float c[4], const unsigned a[4], const unsigned b[2]) {
    asm volatile(
        "mma.sync.aligned.m16n8k16.row.col.f32.f16.f16.f32 "
        "{%0,%1,%2,%3},{%4,%5,%6,%7},{%8,%9},{%0,%1,%2,%3};"
        : "+f"(c[0]), "+f"(c[1]), "+f"(c[2]), "+f"(c[3])
        : "r"(a[0]), "r"(a[1]), "r"(a[2]), "r"(a[3]), "r"(b[0]), "r"(b[1]));
}

// ---------------- zero rowsums ----------------
__global__ __launch_bounds__(256)
void rs_zero(float* __restrict__ rs)
{
    rs[blockIdx.x * 256 + threadIdx.x] = 0.f;
}

// ---------------- X -> fp16 hi/lo ----------------
__global__ __launch_bounds__(256)
void convert_x(const float4* __restrict__ X, __half2* __restrict__ Xh,
               __half2* __restrict__ Xl)
{
    long i = (long)blockIdx.x * 256 + threadIdx.x;
    float4 v = X[i];
    __half hx = __float2half(v.x), hy = __float2half(v.y);
    __half hz = __float2half(v.z), hw = __float2half(v.w);
    __half2 h0, h1, l0, l1;
    h0 = __halves2half2(hx, hy);
    h1 = __halves2half2(hz, hw);
    l0 = __halves2half2(__float2half(v.x - __half2float(hx)),
                        __float2half(v.y - __half2float(hy)));
    l1 = __halves2half2(__float2half(v.z - __half2float(hz)),
                        __float2half(v.w - __half2float(hw)));
    Xh[i * 2]     = h0; Xh[i * 2 + 1] = h1;
    Xl[i * 2]     = l0; Xl[i * 2 + 1] = l1;
}

// ---------------- prep: Qh = fp16(64 * (codes@Wq^T+bq)@Wk), c = q.bk/16 ----------------
__global__ __launch_bounds__(256)
void prep_q(const float* __restrict__ cat, const float* __restrict__ typ,
            const float* __restrict__ var, const float* __restrict__ sp,
            const float* __restrict__ Wcat, const float* __restrict__ bcat,
            const float* __restrict__ Wtype, const float* __restrict__ btype,
            const float* __restrict__ Wvar, const float* __restrict__ bvar,
            const float* __restrict__ Wsp, const float* __restrict__ bsp,
            const float* __restrict__ Wk, const float* __restrict__ bk,
            __half* __restrict__ Qh, float* __restrict__ cvec)
{
    int m = blockIdx.x;
    const float* codes; const float* Wq; const float* bq;
    if (m < 16)       { codes = cat + m * DIM;         Wq = Wcat;  bq = bcat; }
    else if (m < 144) { codes = typ + (m - 16) * DIM;  Wq = Wtype; bq = btype; }
    else if (m < 656) { codes = var + (m - 144) * DIM; Wq = Wvar;  bq = bvar; }
    else              { codes = sp + (m - 656) * DIM;  Wq = Wsp;   bq = bsp; }

    __shared__ float cs[DIM], qs[DIM], red[256];
    int t = threadIdx.x;
    cs[t] = codes[t];
    __syncthreads();

    int w = t >> 5, l = t & 31;
    for (int j = w; j < DIM; j += 8) {
        const float* wr = Wq + j * DIM;
        float s = 0.f;
        #pragma unroll
        for (int i = 0; i < 8; i++) s += wr[l + 32 * i] * cs[l + 32 * i];
        #pragma unroll
        for (int o = 16; o > 0; o >>= 1) s += __shfl_xor_sync(0xffffffffu, s, o);
        if (l == 0) qs[j] = s + bq[j];
    }
    __syncthreads();

    float a = 0.f;
    for (int j = 0; j < DIM; j++) a += qs[j] * Wk[j * DIM + t];
    Qh[m * DIM + t] = __float2half(a * 64.0f);   // (a/16) * 1024

    red[t] = qs[t] * bk[t];
    __syncthreads();
    for (int s = 128; s > 0; s >>= 1) { if (t < s) red[t] += red[t + s]; __syncthreads(); }
    if (t == 0) cvec[m] = red[0] * 0.0625f;
}

// ---------------- logits+exp: E = fp16(exp(clip(acc/1024 + c))), rowsum atomics ----------------
extern __shared__ char dsm[];

__global__ __launch_bounds__(256)
void logits_mma(const __half* __restrict__ Qh,
                const __half* __restrict__ Xh,
                __half* __restrict__ E,
                float* __restrict__ rowsum,
                const float* __restrict__ cvec,
                const unsigned char* __restrict__ mask)
{
    const int SK = 40;
    const int STAGE = 20480;
    const int SE = 136;

    int b = blockIdx.z;
    int m0 = blockIdx.y * 128, n0 = blockIdx.x * 128;
    const __half* Xb = Xh + (long)b * NTOK * DIM;
    int t = threadIdx.x, lane = t & 31, w = t >> 5;
    int wm = (w >> 2) * 64, wn = (w & 3) * 32;
    int l15 = lane & 15, t4 = lane & 3;

    auto load_stage = [&](int kt, int s) {
        char* base = dsm + s * STAGE;
        #pragma unroll
        for (int i = 0; i < 2; i++) {
            int c = t + i * 256;
            int row = c >> 2, kq = c & 3;
            cpa16(sm_u32(base + (row * SK + kq * 8) * 2),
                  Qh + (m0 + row) * DIM + kt * 32 + kq * 8);
            cpa16(sm_u32(base + 10240 + (row * SK + kq * 8) * 2),
                  Xb + (long)(n0 + row) * DIM + kt * 32 + kq * 8);
        }
        cpa_commit();
    };

    float acc[4][4][4] = {};
    load_stage(0, 0);
    for (int kt = 0; kt < 8; kt++) {
        cpa_wait<0>();
        __syncthreads();
        if (kt < 7) load_stage(kt + 1, (kt + 1) & 1);
        char* base = dsm + (kt & 1) * STAGE;
        unsigned aBase = sm_u32(base + ((wm + l15) * SK + (lane >> 4) * 8) * 2);
        unsigned bBase = sm_u32(base + 10240 + ((wn + (l15 & 7)) * SK + (l15 >> 3) * 8) * 2);
        #pragma unroll
        for (int ks = 0; ks < 2; ks++) {
            unsigned a[4][4], bf[4][2];
            #pragma unroll
            for (int mi = 0; mi < 4; mi++) ldsm4(a[mi], aBase + (unsigned)(mi * 16 * SK + ks * 16) * 2u);
            #pragma unroll
            for (int ni = 0; ni < 4; ni++) ldsm2(bf[ni], bBase + (unsigned)(ni * 8 * SK + ks * 16) * 2u);
            #pragma unroll
            for (int mi = 0; mi < 4; mi++)
                #pragma unroll
                for (int ni = 0; ni < 4; ni++) mma16816(acc[mi][ni], a[mi], bf[ni]);
        }
    }
    __syncthreads();   // reuse smem for epilogue staging

    __half* sE = (__half*)dsm;
    const unsigned char* mrow = mask + (long)b * NTOK + n0;
    const float DS = 1.0f / 1024.0f;

    #pragma unroll
    for (int mi = 0; mi < 4; mi++) {
        #pragma unroll
        for (int r = 0; r < 2; r++) {
            int row = wm + mi * 16 + (lane >> 2) + r * 8;
            float cv = cvec[m0 + row];
            float rs = 0.f;
            #pragma unroll
            for (int ni = 0; ni < 4; ni++) {
                int col = wn + ni * 8 + t4 * 2;
                float x0 = acc[mi][ni][r * 2 + 0] * DS + cv;
                float x1 = acc[mi][ni][r * 2 + 1] * DS + cv;
                x0 = fminf(fmaxf(x0, -50.f), 50.f);
                x1 = fminf(fmaxf(x1, -50.f), 50.f);
                if (!mrow[col])     x0 = -50.f;
                if (!mrow[col + 1]) x1 = -50.f;
                float e0 = __expf(x0);
                float e1 = __expf(x1);
                rs += e0 + e1;
                *(__half2*)(sE + row * SE + col) =
                    __halves2half2(__float2half(e0), __float2half(e1));
            }
            rs += __shfl_xor_sync(0xffffffffu, rs, 1);
            rs += __shfl_xor_sync(0xffffffffu, rs, 2);
            if (t4 == 0) atomicAdd(&rowsum[b * MPAD + m0 + row], rs);
        }
    }
    __syncthreads();

    long robase = ((long)b * MPAD + m0) * NTOK + n0;
    #pragma unroll
    for (int i = 0; i < 8; i++) {
        int c = t + i * 256;
        int row = c >> 4, seg = c & 15;
        uint4 vh = *(uint4*)(sE + row * SE + seg * 8);
        *(uint4*)(E + robase + (long)row * NTOK + seg * 8) = vh;
    }
}

// ---------------- H = (E @ X) / rowsum  (fp16, 2 passes: E.Xh + E.Xl) ----------------
__global__ __launch_bounds__(256)
void h_mma(const __half* __restrict__ E,
           const __half* __restrict__ Xh, const __half* __restrict__ Xl,
           const float* __restrict__ rowsum, float* __restrict__ H)
{
    const int SK = 40, SN = 264;
    // stage (halves): A @0 (64*40=2560h=5120B), Bh @5120B (32*264), Bl @22016B
    const int STAGE = 38912;

    int b = blockIdx.z;
    int m0 = blockIdx.y * 64;
    const __half* Eb  = E  + ((long)b * MPAD + m0) * NTOK;
    const __half* Xhb = Xh + (long)b * NTOK * DIM;
    const __half* Xlb = Xl + (long)b * NTOK * DIM;
    int t = threadIdx.x, lane = t & 31, w = t >> 5;
    int wm = (w >> 2) * 32, wd = (w & 3) * 64;
    int l15 = lane & 15;

    auto load_stage = [&](int kt, int s) {
        char* base = dsm + s * STAGE;
        {
            int row = t >> 2, kq = t & 3;
            long off = (long)row * NTOK + kt * 32 + kq * 8;
            cpa16(sm_u32(base + (row * SK + kq * 8) * 2), Eb + off);
        }
        #pragma unroll
        for (int i = 0; i < 4; i++) {
            int c = t + i * 256;
            int kr = c >> 5, nc = (c & 31) * 8;
            long off = (long)(kt * 32 + kr) * DIM + nc;
            cpa16(sm_u32(base + 5120 + (kr * SN + nc) * 2), Xhb + off);
            cpa16(sm_u32(base + 22016 + (kr * SN + nc) * 2), Xlb + off);
        }
        cpa_commit();
    };

    float acc[2][8][4] = {};
    load_stage(0, 0);
    for (int kt = 0; kt < NTOK / 32; kt++) {
        cpa_wait<0>();
        __syncthreads();
        if (kt < NTOK / 32 - 1) load_stage(kt + 1, (kt + 1) & 1);
        char* base = dsm + (kt & 1) * STAGE;
        unsigned aB  = sm_u32(base + ((wm + l15) * SK + (lane >> 4) * 8) * 2);
        unsigned bhB = sm_u32(base + 5120 + (l15 * SN + wd) * 2);
        unsigned blB = bhB + (22016 - 5120);
        #pragma unroll
        for (int ks = 0; ks < 2; ks++) {
            unsigned a[2][4];
            ldsm4(a[0], aB + (unsigned)(0 * 16 * SK + ks * 16) * 2u);
            ldsm4(a[1], aB + (unsigned)(1 * 16 * SK + ks * 16) * 2u);
            #pragma unroll
            for (int nj = 0; nj < 8; nj++) {
                unsigned bh[2], bl[2];
                ldsm2t(bh, bhB + (unsigned)(ks * 16 * SN) * 2u + (unsigned)nj * 16u);
                ldsm2t(bl, blB + (unsigned)(ks * 16 * SN) * 2u + (unsigned)nj * 16u);
                mma16816(acc[0][nj], a[0], bh);
                mma16816(acc[1][nj], a[1], bh);
                mma16816(acc[0][nj], a[0], bl);
                mma16816(acc[1][nj], a[1], bl);
            }
        }
    }

    int g = lane >> 2, t4 = lane & 3;
    #pragma unroll
    for (int mi = 0; mi < 2; mi++) {
        #pragma unroll
        for (int r = 0; r < 2; r++) {
            int row = wm + mi * 16 + g + r * 8;
            float inv = 1.f / rowsum[b * MPAD + m0 + row];
            float* hrow = H + ((long)b * MPAD + m0 + row) * DIM;
            #pragma unroll
            for (int nj = 0; nj < 8; nj++) {
                int col = wd + nj * 8 + t4 * 2;
                *(float2*)(hrow + col) =
                    make_float2(acc[mi][nj][r * 2 + 0] * inv,
                                acc[mi][nj][r * 2 + 1] * inv);
            }
        }
    }
}

// ---------------- row norms ----------------
__global__ __launch_bounds__(256)
void norms_kernel(const float* __restrict__ H, const float* __restrict__ log_tau,
                  float* __restrict__ sw)
{
    int b = blockIdx.y;
    int m = blockIdx.x * 8 + (threadIdx.x >> 5);
    int l = threadIdx.x & 31;
    float tau = fminf(fmaxf(expf(log_tau[0]) + 0.1f, 0.1f), 2.0f);
    const float* hr = H + ((long)b * MPAD + m) * DIM;
    float s = 0.f;
    #pragma unroll
    for (int i = 0; i < 8; i++) { float x = hr[l + 32 * i]; s += x * x; }
    #pragma unroll
    for (int o = 16; o > 0; o >>= 1) s += __shfl_xor_sync(0xffffffffu, s, o);
    if (l == 0) sw[b * M_TOT + m] = sqrtf(s) / tau;
}

// ---------------- per-batch tail ----------------
__device__ __forceinline__ float blk_sum(float v, float* red, int t)
{
    __syncthreads();
    red[t] = v; __syncthreads();
    for (int s = 128; s > 0; s >>= 1) { if (t < s) red[t] += red[t + s]; __syncthreads(); }
    float r = red[0]; __syncthreads();
    return r;
}
__device__ __forceinline__ float blk_max(float v, float* red, int t)
{
    __syncthreads();
    red[t] = v; __syncthreads();
    for (int s = 128; s > 0; s >>= 1) { if (t < s) red[t] = fmaxf(red[t], red[t + s]); __syncthreads(); }
    float r = red[0]; __syncthreads();
    return r;
}
__device__ void softmax_sparsify(float* a, int len, float thr, float* red, int t)
{
    float m = -1e30f;
    for (int i = t; i < len; i += 256) m = fmaxf(m, a[i]);
    m = blk_max(m, red, t);
    float s = 0.f;
    for (int i = t; i < len; i += 256) { float e = expf(a[i] - m); a[i] = e; s += e; }
    s = blk_sum(s, red, t);
    float inv = 1.f / s;
    float s2 = 0.f;
    for (int i = t; i < len; i += 256) { float p = a[i] * inv; p = (p > thr) ? p : 0.f; a[i] = p; s2 += p; }
    s2 = blk_sum(s2, red, t);
    float inv2 = 1.f / (s2 + 1e-8f);
    for (int i = t; i < len; i += 256) a[i] *= inv2;
    __syncthreads();
}

__global__ __launch_bounds__(256)
void final_kernel(const float* __restrict__ H, const float* __restrict__ swg,
                  const float* __restrict__ part,
                  const float* __restrict__ cnt,
                  const float* __restrict__ Wg1, const float* __restrict__ bg1,
                  const float* __restrict__ Wg2, const float* __restrict__ bg2,
                  const float* __restrict__ Wo,  const float* __restrict__ bo,
                  const float* __restrict__ ln_g, const float* __restrict__ ln_b,
                  const float* __restrict__ lvlw, float* __restrict__ out)
{
    __shared__ float red[256];
    __shared__ float wcs[16], wts[128], wvs[512], wss[16];
    __shared__ float coeff[M_TOT];
    __shared__ float xc[512];
    __shared__ float hb[256], gb[256], yb[256], zg[256];
    __shared__ float lw[4];

    int b = blockIdx.x;
    int t = threadIdx.x;
    const float* Hb = H + (long)b * MPAD * DIM;
    const float* sw = swg + b * M_TOT;

    if (t == 0) {
        float m = fmaxf(fmaxf(lvlw[0], lvlw[1]), fmaxf(lvlw[2], lvlw[3]));
        float e0 = expf(lvlw[0]-m), e1 = expf(lvlw[1]-m), e2 = expf(lvlw[2]-m), e3 = expf(lvlw[3]-m);
        float s = e0+e1+e2+e3;
        lw[0]=e0/s; lw[1]=e1/s; lw[2]=e2/s; lw[3]=e3/s;
    }

    if (t < 16) wcs[t] = sw[t];
    __syncthreads();
    softmax_sparsify(wcs, 16, 0.1f, red, t);
    if (t < 128) wts[t] = sw[16 + t] * wcs[t >> 3];
    __syncthreads();
    softmax_sparsify(wts, 128, 0.05f, red, t);
    for (int i = t; i < 512; i += 256) wvs[i] = sw[144 + i] * wts[i >> 2];
    __syncthreads();
    softmax_sparsify(wvs, 512, 0.025f, red, t);
    if (t < 16) wss[t] = sw[656 + t];
    __syncthreads();
    softmax_sparsify(wss, 16, 0.1f, red, t);

    for (int i = t; i < M_TOT; i += 256) {
        float c;
        if (i < 16)       c = lw[0] * wcs[i];
        else if (i < 144) c = lw[1] * wts[i - 16];
        else if (i < 656) c = lw[2] * wvs[i - 144];
        else              c = lw[3] * wss[i - 656];
        coeff[i] = c;
    }
    __syncthreads();

    {
        float z0 = 0.f, z1 = 0.f, z2 = 0.f, z3 = 0.f;
        float z4 = 0.f, z5 = 0.f, z6 = 0.f, z7 = 0.f;
        #pragma unroll 2
        for (int m = 0; m < M_TOT; m += 8) {
            z0 += coeff[m]     * Hb[(m)     * DIM + t];
            z1 += coeff[m + 1] * Hb[(m + 1) * DIM + t];
            z2 += coeff[m + 2] * Hb[(m + 2) * DIM + t];
            z3 += coeff[m + 3] * Hb[(m + 3) * DIM + t];
            z4 += coeff[m + 4] * Hb[(m + 4) * DIM + t];
            z5 += coeff[m + 5] * Hb[(m + 5) * DIM + t];
            z6 += coeff[m + 6] * Hb[(m + 6) * DIM + t];
            z7 += coeff[m + 7] * Hb[(m + 7) * DIM + t];
        }
        xc[t] = ((z0 + z1) + (z2 + z3)) + ((z4 + z5) + (z6 + z7));
    }

    float pp = 0.f, cc = 0.f;
    #pragma unroll
    for (int s = 0; s < 16; s++) {
        pp += part[((long)b * 16 + s) * DIM + t];
        cc += cnt[b * 16 + s];
    }
    xc[256 + t] = pp / (cc + 1e-8f);
    __syncthreads();

    int w = t >> 5, l = t & 31;
    for (int j = w; j < 256; j += 8) {
        const float* wr = Wg1 + j * 512;
        float s = 0.f;
        #pragma unroll
        for (int i = 0; i < 16; i++) s += wr[l + 32 * i] * xc[l + 32 * i];
        #pragma unroll
        for (int o = 16; o > 0; o >>= 1) s += __shfl_xor_sync(0xffffffffu, s, o);
        if (l == 0) {
            float x = s + bg1[j];
            hb[j] = 0.5f * x * (1.0f + erff(x * 0.70710678118654752f));
        }
    }
    __syncthreads();

    for (int j = w; j < 256; j += 8) {
        const float* wr = Wg2 + j * 256;
        float s = 0.f;
        #pragma unroll
        for (int i = 0; i < 8; i++) s += wr[l + 32 * i] * hb[l + 32 * i];
        #pragma unroll
        for (int o = 16; o > 0; o >>= 1) s += __shfl_xor_sync(0xffffffffu, s, o);
        if (l == 0) gb[j] = 1.0f / (1.0f + expf(-(s + bg2[j])));
    }
    __syncthreads();

    zg[t] = xc[t] * gb[t];
    __syncthreads();

    for (int j = w; j < 256; j += 8) {
        const float* wr = Wo + j * 256;
        float s = 0.f;
        #pragma unroll
        for (int i = 0; i < 8; i++) s += wr[l + 32 * i] * zg[l + 32 * i];
        #pragma unroll
        for (int o = 16; o > 0; o >>= 1) s += __shfl_xor_sync(0xffffffffu, s, o);
        if (l == 0) yb[j] = s + bo[j];
    }
    __syncthreads();

    float y = yb[t];
    float mu = blk_sum(y, red, t) * (1.0f / 256.0f);
    float d0 = y - mu;
    float var = blk_sum(d0 * d0, red, t) * (1.0f / 256.0f);
    out[(long)b * DIM + t] = d0 * rsqrtf(var + 1e-5f) * ln_g[t] + ln_b[t];
}

// ---------------- masked position pooling partials ----------------
__global__ __launch_bounds__(256)
void pospool_partial(const float* __restrict__ pos, const unsigned char* __restrict__ mask,
                     float* __restrict__ part, float* __restrict__ cnt)
{
    int s = blockIdx.x, b = blockIdx.y;
    int t = threadIdx.x;
    const float* P = pos + ((long)b * NTOK + s * 256) * DIM;
    const unsigned char* M = mask + (long)b * NTOK + s * 256;
    float acc = 0.f, c = 0.f;
    for (int n = 0; n < 256; n++) {
        float mm = M[n] ? 1.f : 0.f;
        c += mm;
        acc += mm * P[(long)n * DIM + t];
    }
    part[((long)b * 16 + s) * DIM + t] = acc;
    if (t == 0) cnt[b * 16 + s] = c;
}

// ---------------- launch ----------------
extern "C" void kernel_launch(void* const* d_in, const int* in_sizes, int n_in,
                              void* d_out, int out_size)
{
    const float* X    = (const float*)d_in[0];
    const float* pos  = (const float*)d_in[1];
    const unsigned char* mask = (const unsigned char*)d_in[2];
    const float* cat  = (const float*)d_in[3];
    const float* typ  = (const float*)d_in[4];
    const float* var  = (const float*)d_in[5];
    const float* sp   = (const float*)d_in[6];
    const float* log_tau = (const float*)d_in[7];
    const float* Wk   = (const float*)d_in[8];
    const float* bk   = (const float*)d_in[9];
    const float* Wcat = (const float*)d_in[10];
    const float* bcat = (const float*)d_in[11];
    const float* Wtype= (const float*)d_in[12];
    const float* btype= (const float*)d_in[13];
    const float* Wvar = (const float*)d_in[14];
    const float* bvar = (const float*)d_in[15];
    const float* Wsp  = (const float*)d_in[16];
    const float* bsp  = (const float*)d_in[17];
    const float* Wg1  = (const float*)d_in[18];
    const float* bg1  = (const float*)d_in[19];
    const float* Wg2  = (const float*)d_in[20];
    const float* bg2  = (const float*)d_in[21];
    const float* Wo   = (const float*)d_in[22];
    const float* bo   = (const float*)d_in[23];
    const float* ln_g = (const float*)d_in[24];
    const float* ln_b = (const float*)d_in[25];
    const float* lvlw = (const float*)d_in[26];
    float* out = (float*)d_out;

    __half *Qh, *E, *Xh, *Xl;
    float *cvec, *rs, *H, *sw, *part, *cnt;
    cudaGetSymbolAddress((void**)&Qh,   g_Qh);
    cudaGetSymbolAddress((void**)&cvec, g_c);
    cudaGetSymbolAddress((void**)&E,    g_E);
    cudaGetSymbolAddress((void**)&Xh,   g_Xh);
    cudaGetSymbolAddress((void**)&Xl,   g_Xl);
    cudaGetSymbolAddress((void**)&rs,   g_rs);
    cudaGetSymbolAddress((void**)&H,    g_H);
    cudaGetSymbolAddress((void**)&sw,   g_sw);
    cudaGetSymbolAddress((void**)&part, g_part);
    cudaGetSymbolAddress((void**)&cnt,  g_cnt);

    cudaFuncSetAttribute(logits_mma, cudaFuncAttributeMaxDynamicSharedMemorySize, 40960);
    cudaFuncSetAttribute(h_mma,      cudaFuncAttributeMaxDynamicSharedMemorySize, 77824);

    // 1) X -> fp16 hi/lo
    {
        long n4 = (long)BATCH * NTOK * DIM / 4;
        convert_x<<<(unsigned)(n4 / 256), 256>>>((const float4*)X,
                                                 (__half2*)Xh, (__half2*)Xl);
    }

    // 2) Q' and c ; zero rowsums
    prep_q<<<M_TOT, 256>>>(cat, typ, var, sp, Wcat, bcat, Wtype, btype,
                           Wvar, bvar, Wsp, bsp, Wk, bk, Qh, cvec);
    rs_zero<<<(BATCH * MPAD) / 256, 256>>>(rs);

    // 3) logits -> exp (fp16) + row sums
    {
        dim3 grid(NTOK / 128, MPAD / 128, BATCH);
        logits_mma<<<grid, 256, 40960>>>(Qh, Xh, E, rs, cvec, mask);
    }

    // 4) H = (E @ X) / rowsum (fp16, 2 passes)
    {
        dim3 grid(1, 11, BATCH);
        h_mma<<<grid, 256, 77824>>>(E, Xh, Xl, rs, H);
    }

    // 5) position pooling partials
    {
        dim3 grid(16, BATCH);
        pospool_partial<<<grid, 256>>>(pos, mask, part, cnt);
    }

    // 6) row norms
    {
        dim3 grid(M_TOT / 8, BATCH);
        norms_kernel<<<grid, 256>>>(H, log_tau, sw);
    }

    // 7) per-batch tail
    final_kernel<<<BATCH, 256>>>(H, sw, part, cnt,
                                 Wg1, bg1, Wg2, bg2, Wo, bo,
                                 ln_g, ln_b, lvlw, out);
}